// round 1
// baseline (speedup 1.0000x reference)
#include <cuda_runtime.h>
#include <cstddef>

// ---------------- problem constants ----------------
#define BATCH   8
#define IMG     384
#define CIN     3
#define PATCH   16
#define GRID    24          // IMG/PATCH
#define LTOK    576         // GRID*GRID
#define WDIM    768
#define DEPTH   4
#define NHEAD   12
#define HDIM    64
#define MLPDIM  3072
#define NROWS   (BATCH*LTOK)        // 4608
#define EPS     1e-6f

// ---------------- scratch (static device globals; no allocations) ----------------
__device__ float g_x [NROWS*WDIM];
__device__ float g_y [NROWS*WDIM];
__device__ float g_q [NROWS*WDIM];
__device__ float g_k [NROWS*WDIM];
__device__ float g_v [NROWS*WDIM];
__device__ float g_o [NROWS*WDIM];
__device__ float g_h1[NROWS*MLPDIM];        // also reused as im2col buffer
__device__ float g_rope[4*LTOK*16];         // cosx,sinx,cosy,siny each [576][16]

// ---------------- helpers ----------------
__device__ __forceinline__ float gelu_f(float x) {
    float x3 = x*x*x;
    return 0.5f*x*(1.f + tanhf(0.7978845608028654f*(x + 0.044715f*x3)));
}

// ---------------- im2col for patch embed ----------------
__global__ void im2col_k(const float* __restrict__ img, float* __restrict__ out) {
    int idx = blockIdx.x*256 + threadIdx.x;
    if (idx >= NROWS*WDIM) return;
    int t  = idx % WDIM;       // (i*16+j)*3+ci
    int nl = idx / WDIM;
    int l  = nl % LTOK;
    int n  = nl / LTOK;
    int ci = t % 3;
    int ij = t / 3;
    int j  = ij % PATCH;
    int i  = ij / PATCH;
    int px = l % GRID, py = l / GRID;
    out[idx] = img[ (((size_t)n*IMG + (py*PATCH+i))*IMG + (px*PATCH+j))*CIN + ci ];
}

// ---------------- rope cache ----------------
__global__ void rope_cache_k(float* __restrict__ cache) {
    int idx = blockIdx.x*256 + threadIdx.x;
    if (idx >= LTOK*16) return;
    int f = idx % 16, l = idx / 16;
    float freq = (float)f / (15.f + 1e-9f);
    float inv  = powf(10000.f, -freq);
    float u = ((float)(l % GRID) + 0.5f) / (float)GRID;
    float v = ((float)(l / GRID) + 0.5f) / (float)GRID;
    float ax = u*inv, ay = v*inv;
    cache[0*LTOK*16 + idx] = cosf(ax);
    cache[1*LTOK*16 + idx] = sinf(ax);
    cache[2*LTOK*16 + idx] = cosf(ay);
    cache[3*LTOK*16 + idx] = sinf(ay);
}

// ---------------- rope apply (in-place on q or k) ----------------
__global__ void rope_apply_k(float* __restrict__ q, const float* __restrict__ cache) {
    int idx = blockIdx.x*256 + threadIdx.x;     // over n*L*H*32 pairs
    const int TOT = BATCH*LTOK*NHEAD*32;
    if (idx >= TOT) return;
    int p  = idx % 32;
    int h  = (idx/32) % NHEAD;
    int l  = (idx/(32*NHEAD)) % LTOK;
    int n  = idx/(32*NHEAD*LTOK);
    float c, s;
    if (p < 16) { c = cache[0*LTOK*16 + l*16 + p];    s = cache[1*LTOK*16 + l*16 + p]; }
    else        { c = cache[2*LTOK*16 + l*16 + p-16]; s = cache[3*LTOK*16 + l*16 + p-16]; }
    float* ptr = q + (((size_t)(n*LTOK+l)*NHEAD + h)*HDIM) + 2*p;
    float x = ptr[0], y = ptr[1];
    ptr[0] = x*c - y*s;
    ptr[1] = x*s + y*c;
}

// ---------------- layernorm (row = 768) ----------------
__global__ void ln_k(const float* __restrict__ x, float* __restrict__ y,
                     const float* __restrict__ sc, const float* __restrict__ bi) {
    int row = blockIdx.x;
    const float* xr = x + (size_t)row*WDIM;
    float*       yr = y + (size_t)row*WDIM;
    int tid = threadIdx.x;                       // 256 threads, 3 elems each
    float v0 = xr[tid], v1 = xr[tid+256], v2 = xr[tid+512];
    float s  = v0+v1+v2;
    float sq = v0*v0 + v1*v1 + v2*v2;
    #pragma unroll
    for (int o = 16; o; o >>= 1) {
        s  += __shfl_xor_sync(0xffffffffu, s,  o);
        sq += __shfl_xor_sync(0xffffffffu, sq, o);
    }
    __shared__ float ss[8], sqs[8];
    __shared__ float smean, sinv;
    int wid = tid >> 5, lane = tid & 31;
    if (lane == 0) { ss[wid] = s; sqs[wid] = sq; }
    __syncthreads();
    if (tid == 0) {
        float S = 0.f, Q = 0.f;
        #pragma unroll
        for (int i = 0; i < 8; i++) { S += ss[i]; Q += sqs[i]; }
        float m  = S / (float)WDIM;
        float var = Q / (float)WDIM - m*m;
        smean = m;
        sinv  = rsqrtf(var + EPS);
    }
    __syncthreads();
    float m = smean, inv = sinv;
    yr[tid]     = (v0 - m)*inv*sc[tid]     + bi[tid];
    yr[tid+256] = (v1 - m)*inv*sc[tid+256] + bi[tid+256];
    yr[tid+512] = (v2 - m)*inv*sc[tid+512] + bi[tid+512];
}

// ---------------- tiled SGEMM: C = A[M,K]*B[K,N] + bias (+gelu) (+residual) ----------------
template<bool GELU_F, bool RES>
__global__ void __launch_bounds__(256, 2)
gemm_k(const float* __restrict__ A, const float* __restrict__ B,
       const float* __restrict__ bias, const float* __restrict__ R,
       float* __restrict__ C, int M, int N, int K) {
    __shared__ float As[8][128];
    __shared__ float Bs[8][128];
    int tid = threadIdx.x;
    int bn = blockIdx.x * 128, bm = blockIdx.y * 128;
    int tx = tid & 15, ty = tid >> 4;
    int arow = tid >> 1, acol = (tid & 1) << 2;
    int brow = tid >> 5, bcol = (tid & 31) << 2;
    const float* Ap = A + (size_t)(bm + arow)*K + acol;
    const float* Bp = B + (size_t)brow*N + bn + bcol;
    float acc[8][8];
    #pragma unroll
    for (int i = 0; i < 8; i++)
        #pragma unroll
        for (int j = 0; j < 8; j++) acc[i][j] = 0.f;

    for (int k0 = 0; k0 < K; k0 += 8) {
        float4 av = *(const float4*)(Ap + k0);
        float4 bv = *(const float4*)(Bp + (size_t)k0*N);
        As[acol  ][arow] = av.x;
        As[acol+1][arow] = av.y;
        As[acol+2][arow] = av.z;
        As[acol+3][arow] = av.w;
        *(float4*)&Bs[brow][bcol] = bv;
        __syncthreads();
        #pragma unroll
        for (int kk = 0; kk < 8; kk++) {
            float ra[8], rb[8];
            *(float4*)(ra)   = *(const float4*)&As[kk][ty*8];
            *(float4*)(ra+4) = *(const float4*)&As[kk][ty*8+4];
            *(float4*)(rb)   = *(const float4*)&Bs[kk][tx*8];
            *(float4*)(rb+4) = *(const float4*)&Bs[kk][tx*8+4];
            #pragma unroll
            for (int i = 0; i < 8; i++)
                #pragma unroll
                for (int j = 0; j < 8; j++)
                    acc[i][j] = fmaf(ra[i], rb[j], acc[i][j]);
        }
        __syncthreads();
    }
    #pragma unroll
    for (int i = 0; i < 8; i++) {
        int m = bm + ty*8 + i;
        #pragma unroll
        for (int j = 0; j < 8; j++) {
            int n = bn + tx*8 + j;
            float v = acc[i][j] + bias[n];
            if (GELU_F) v = gelu_f(v);
            if (RES)    v += R[(size_t)m*N + n];
            C[(size_t)m*N + n] = v;
        }
    }
}

// ---------------- fused attention: softmax(qK^T/8) V per (n,h,q) ----------------
__global__ void attn_k(const float* __restrict__ Q, const float* __restrict__ K,
                       const float* __restrict__ V, float* __restrict__ O) {
    int b  = blockIdx.x;           // (n*12+h)*576 + qi  -> same (n,h) adjacent for L2 reuse
    int qi = b % LTOK;
    int nh = b / LTOK;
    int h  = nh % NHEAD;
    int n  = nh / NHEAD;
    int tid = threadIdx.x;         // 256
    __shared__ float sq[64];
    __shared__ float sp[LTOK];
    __shared__ float red[256];

    const float* qp = Q + ((size_t)(n*LTOK + qi)*NHEAD + h)*HDIM;
    if (tid < 64) sq[tid] = qp[tid];
    __syncthreads();

    float lmax = -1e30f;
    for (int k = tid; k < LTOK; k += 256) {
        const float4* kp = (const float4*)(K + ((size_t)(n*LTOK + k)*NHEAD + h)*HDIM);
        float dot = 0.f;
        #pragma unroll
        for (int d = 0; d < 16; d++) {
            float4 kv = kp[d];
            dot += sq[4*d]*kv.x + sq[4*d+1]*kv.y + sq[4*d+2]*kv.z + sq[4*d+3]*kv.w;
        }
        dot *= 0.125f;
        sp[k] = dot;
        lmax = fmaxf(lmax, dot);
    }
    red[tid] = lmax; __syncthreads();
    for (int s = 128; s; s >>= 1) { if (tid < s) red[tid] = fmaxf(red[tid], red[tid+s]); __syncthreads(); }
    float mx = red[0];
    __syncthreads();

    float lsum = 0.f;
    for (int k = tid; k < LTOK; k += 256) {
        float e = __expf(sp[k] - mx);
        sp[k] = e;
        lsum += e;
    }
    red[tid] = lsum; __syncthreads();
    for (int s = 128; s; s >>= 1) { if (tid < s) red[tid] += red[tid+s]; __syncthreads(); }
    float inv = 1.f / red[0];

    int d = tid & 63, part = tid >> 6;
    float acc = 0.f;
    for (int k = part; k < LTOK; k += 4)
        acc += sp[k] * V[((size_t)(n*LTOK + k)*NHEAD + h)*HDIM + d];
    __syncthreads();
    red[tid] = acc; __syncthreads();
    if (part == 0) {
        float o = (red[d] + red[64+d] + red[128+d] + red[192+d]) * inv;
        O[((size_t)(n*LTOK + qi)*NHEAD + h)*HDIM + d] = o;
    }
}

// ---------------- final mean over tokens ----------------
__global__ void mean_k(const float* __restrict__ y, float* __restrict__ out) {
    int c = blockIdx.x*256 + threadIdx.x;     // 768 cols -> 3 blocks
    int n = blockIdx.y;
    if (c >= WDIM) return;
    float acc = 0.f;
    for (int l = 0; l < LTOK; l++)
        acc += y[(size_t)(n*LTOK + l)*WDIM + c];
    out[(size_t)n*WDIM + c] = acc * (1.f/(float)LTOK);
}

// ---------------- host orchestration ----------------
extern "C" void kernel_launch(void* const* d_in, const int* in_sizes, int n_in,
                              void* d_out, int out_size) {
    const float* image     = (const float*)d_in[0];
    const float* conv_ker  = (const float*)d_in[1];
    const float* conv_bias = (const float*)d_in[2];
    const float* ln1_scale = (const float*)d_in[3];
    const float* ln1_bias  = (const float*)d_in[4];
    const float* wq        = (const float*)d_in[5];
    const float* bq        = (const float*)d_in[6];
    const float* wk        = (const float*)d_in[7];
    const float* bk        = (const float*)d_in[8];
    const float* wv        = (const float*)d_in[9];
    const float* bv        = (const float*)d_in[10];
    const float* wo        = (const float*)d_in[11];
    const float* bo        = (const float*)d_in[12];
    const float* ln2_scale = (const float*)d_in[13];
    const float* ln2_bias  = (const float*)d_in[14];
    const float* w1        = (const float*)d_in[15];
    const float* b1        = (const float*)d_in[16];
    const float* w2        = (const float*)d_in[17];
    const float* b2        = (const float*)d_in[18];
    const float* lnf_scale = (const float*)d_in[19];
    const float* lnf_bias  = (const float*)d_in[20];
    float* out = (float*)d_out;

    float *x, *y, *q, *k, *v, *o, *h1, *rope;
    cudaGetSymbolAddress((void**)&x,    g_x);
    cudaGetSymbolAddress((void**)&y,    g_y);
    cudaGetSymbolAddress((void**)&q,    g_q);
    cudaGetSymbolAddress((void**)&k,    g_k);
    cudaGetSymbolAddress((void**)&v,    g_v);
    cudaGetSymbolAddress((void**)&o,    g_o);
    cudaGetSymbolAddress((void**)&h1,   g_h1);
    cudaGetSymbolAddress((void**)&rope, g_rope);

    // rope cache
    rope_cache_k<<<(LTOK*16 + 255)/256, 256>>>(rope);

    // patch embed: im2col (into h1 scratch) then GEMM -> x
    im2col_k<<<(NROWS*WDIM + 255)/256, 256>>>(image, h1);
    {
        dim3 g(WDIM/128, NROWS/128);
        gemm_k<false,false><<<g, 256>>>(h1, conv_ker, conv_bias, nullptr, x,
                                        NROWS, WDIM, WDIM);
    }

    dim3 gProj(WDIM/128, NROWS/128);     // 6 x 36
    dim3 gMlp1(MLPDIM/128, NROWS/128);   // 24 x 36
    const int ropeTot = BATCH*LTOK*NHEAD*32;

    for (int l = 0; l < DEPTH; l++) {
        const float* wq_l = wq + (size_t)l*WDIM*WDIM;
        const float* wk_l = wk + (size_t)l*WDIM*WDIM;
        const float* wv_l = wv + (size_t)l*WDIM*WDIM;
        const float* wo_l = wo + (size_t)l*WDIM*WDIM;
        const float* w1_l = w1 + (size_t)l*WDIM*MLPDIM;
        const float* w2_l = w2 + (size_t)l*MLPDIM*WDIM;
        const float* bq_l = bq + (size_t)l*WDIM;
        const float* bk_l = bk + (size_t)l*WDIM;
        const float* bv_l = bv + (size_t)l*WDIM;
        const float* bo_l = bo + (size_t)l*WDIM;
        const float* b1_l = b1 + (size_t)l*MLPDIM;
        const float* b2_l = b2 + (size_t)l*WDIM;

        ln_k<<<NROWS, 256>>>(x, y, ln1_scale + (size_t)l*WDIM, ln1_bias + (size_t)l*WDIM);

        gemm_k<false,false><<<gProj, 256>>>(y, wq_l, bq_l, nullptr, q, NROWS, WDIM, WDIM);
        gemm_k<false,false><<<gProj, 256>>>(y, wk_l, bk_l, nullptr, k, NROWS, WDIM, WDIM);
        gemm_k<false,false><<<gProj, 256>>>(y, wv_l, bv_l, nullptr, v, NROWS, WDIM, WDIM);

        rope_apply_k<<<(ropeTot + 255)/256, 256>>>(q, rope);
        rope_apply_k<<<(ropeTot + 255)/256, 256>>>(k, rope);

        attn_k<<<BATCH*NHEAD*LTOK, 256>>>(q, k, v, o);

        // x = x + o @ wo + bo   (in-place residual)
        gemm_k<false,true><<<gProj, 256>>>(o, wo_l, bo_l, x, x, NROWS, WDIM, WDIM);

        ln_k<<<NROWS, 256>>>(x, y, ln2_scale + (size_t)l*WDIM, ln2_bias + (size_t)l*WDIM);

        gemm_k<true,false><<<gMlp1, 256>>>(y, w1_l, b1_l, nullptr, h1, NROWS, MLPDIM, WDIM);
        gemm_k<false,true><<<gProj, 256>>>(h1, w2_l, b2_l, x, x, NROWS, WDIM, MLPDIM);
    }

    ln_k<<<NROWS, 256>>>(x, y, lnf_scale, lnf_bias);
    {
        dim3 g((WDIM + 255)/256, BATCH);
        mean_k<<<g, 256>>>(y, out);
    }
}

// round 3
// speedup vs baseline: 4.1657x; 4.1657x over previous
#include <cuda_runtime.h>
#include <cuda_bf16.h>
#include <cstdint>
#include <cstddef>

// ---------------- problem constants ----------------
#define BATCH   8
#define IMG     384
#define CIN     3
#define PATCH   16
#define GRIDP   24          // IMG/PATCH
#define LTOK    576         // GRIDP*GRIDP
#define WDIM    768
#define DEPTH   4
#define NHEAD   12
#define HDIM    64
#define MLPDIM  3072
#define NROWS   (BATCH*LTOK)        // 4608
#define EPS     1e-6f

typedef __nv_bfloat16 bf16;

// ---------------- PTX helpers (plain sm_103 — NO tcgen05) ----------------
__device__ __forceinline__ uint32_t smem_to_u32(const void* smem_ptr) {
    uint32_t addr;
    asm("{ .reg .u64 tmp; cvta.to.shared.u64 tmp, %1; cvt.u32.u64 %0, tmp; }"
        : "=r"(addr) : "l"(smem_ptr));
    return addr;
}
#define CP_ASYNC16(dst, src) \
    asm volatile("cp.async.cg.shared.global [%0], [%1], 16;" :: "r"(dst), "l"(src) : "memory")
#define CP_COMMIT() asm volatile("cp.async.commit_group;" ::: "memory")
#define CP_WAIT2()  asm volatile("cp.async.wait_group 2;" ::: "memory")

#define LDSM_X4(r, addr) \
    asm volatile("ldmatrix.sync.aligned.m8n8.x4.shared.b16 {%0,%1,%2,%3}, [%4];" \
        : "=r"((r)[0]), "=r"((r)[1]), "=r"((r)[2]), "=r"((r)[3]) : "r"(addr))

#define MMA16816(d, a, b0, b1) \
    asm volatile("mma.sync.aligned.m16n8k16.row.col.f32.bf16.bf16.f32 " \
        "{%0,%1,%2,%3}, {%4,%5,%6,%7}, {%8,%9}, {%0,%1,%2,%3};" \
        : "+f"((d)[0]), "+f"((d)[1]), "+f"((d)[2]), "+f"((d)[3]) \
        : "r"((a)[0]), "r"((a)[1]), "r"((a)[2]), "r"((a)[3]), "r"(b0), "r"(b1))

#define SWZ(off) ((off) ^ (((off) >> 3) & 0x70))

// ---------------- scratch (static device globals; no allocations) ----------------
__device__ __align__(256) float g_x [NROWS*WDIM];
__device__ __align__(256) float g_y [NROWS*WDIM];
__device__ __align__(256) float g_q [NROWS*WDIM];
__device__ __align__(256) float g_k [NROWS*WDIM];
__device__ __align__(256) float g_v [NROWS*WDIM];
__device__ __align__(256) float g_rope[4*LTOK*16];

__device__ __align__(256) bf16 g_yh [NROWS*WDIM];
__device__ __align__(256) bf16 g_yl [NROWS*WDIM];
__device__ __align__(256) bf16 g_oh [NROWS*WDIM];
__device__ __align__(256) bf16 g_ol [NROWS*WDIM];
__device__ __align__(256) bf16 g_h1h[NROWS*MLPDIM];    // also reused as im2col split
__device__ __align__(256) bf16 g_h1l[NROWS*MLPDIM];

#define SZ_PROJ (768*768)
#define SZ_MLP  (768*3072)
#define WBUF_TOTAL (SZ_PROJ + DEPTH*(4*SZ_PROJ + 2*SZ_MLP))
__device__ __align__(256) bf16 g_whi[WBUF_TOTAL];
__device__ __align__(256) bf16 g_wlo[WBUF_TOTAL];

// ---------------- small helpers ----------------
__device__ __forceinline__ float gelu_f(float x) {
    float x3 = x*x*x;
    return 0.5f*x*(1.f + tanhf(0.7978845608028654f*(x + 0.044715f*x3)));
}
__device__ __forceinline__ void split1(float v, bf16& h, bf16& l) {
    h = __float2bfloat16_rn(v);
    l = __float2bfloat16_rn(v - __bfloat162float(h));
}

// ---------------- transpose + bf16 hi/lo split of weights: W[K,N] -> [N,K] ----------------
__global__ void transcvt_k(const float* __restrict__ W, bf16* __restrict__ hi,
                           bf16* __restrict__ lo, int K, int N) {
    __shared__ float t[32][33];
    int bn = blockIdx.x*32, bk = blockIdx.y*32;
    int x = threadIdx.x, y = threadIdx.y;           // 32 x 8
    #pragma unroll
    for (int r = 0; r < 4; r++)
        t[y*4+r][x] = W[(size_t)(bk + y*4 + r)*N + bn + x];
    __syncthreads();
    #pragma unroll
    for (int r = 0; r < 4; r++) {
        float v = t[x][y*4+r];
        size_t o = (size_t)(bn + y*4 + r)*K + bk + x;
        bf16 h, l; split1(v, h, l);
        hi[o] = h; lo[o] = l;
    }
}

// ---------------- im2col (split bf16 out) ----------------
__global__ void im2col_k(const float* __restrict__ img, bf16* __restrict__ oh,
                         bf16* __restrict__ ol) {
    int idx = blockIdx.x*256 + threadIdx.x;
    if (idx >= NROWS*WDIM) return;
    int t  = idx % WDIM;
    int nl = idx / WDIM;
    int l  = nl % LTOK;
    int n  = nl / LTOK;
    int ci = t % 3;
    int ij = t / 3;
    int j  = ij % PATCH;
    int i  = ij / PATCH;
    int px = l % GRIDP, py = l / GRIDP;
    float v = img[ (((size_t)n*IMG + (py*PATCH+i))*IMG + (px*PATCH+j))*CIN + ci ];
    bf16 h, lo_; split1(v, h, lo_);
    oh[idx] = h; ol[idx] = lo_;
}

// ---------------- rope cache / apply ----------------
__global__ void rope_cache_k(float* __restrict__ cache) {
    int idx = blockIdx.x*256 + threadIdx.x;
    if (idx >= LTOK*16) return;
    int f = idx % 16, l = idx / 16;
    float freq = (float)f / (15.f + 1e-9f);
    float inv  = powf(10000.f, -freq);
    float u = ((float)(l % GRIDP) + 0.5f) / (float)GRIDP;
    float v = ((float)(l / GRIDP) + 0.5f) / (float)GRIDP;
    float ax = u*inv, ay = v*inv;
    cache[0*LTOK*16 + idx] = cosf(ax);
    cache[1*LTOK*16 + idx] = sinf(ax);
    cache[2*LTOK*16 + idx] = cosf(ay);
    cache[3*LTOK*16 + idx] = sinf(ay);
}
__global__ void rope_apply_k(float* __restrict__ q, const float* __restrict__ cache) {
    int idx = blockIdx.x*256 + threadIdx.x;
    const int TOT = BATCH*LTOK*NHEAD*32;
    if (idx >= TOT) return;
    int p  = idx % 32;
    int h  = (idx/32) % NHEAD;
    int l  = (idx/(32*NHEAD)) % LTOK;
    int n  = idx/(32*NHEAD*LTOK);
    float c, s;
    if (p < 16) { c = cache[0*LTOK*16 + l*16 + p];    s = cache[1*LTOK*16 + l*16 + p]; }
    else        { c = cache[2*LTOK*16 + l*16 + p-16]; s = cache[3*LTOK*16 + l*16 + p-16]; }
    float* ptr = q + (((size_t)(n*LTOK+l)*NHEAD + h)*HDIM) + 2*p;
    float x = ptr[0], y = ptr[1];
    ptr[0] = x*c - y*s;
    ptr[1] = x*s + y*c;
}

// ---------------- layernorm (row = 768): fp32 out + split bf16 out ----------------
__global__ void ln_k(const float* __restrict__ x, float* __restrict__ y,
                     bf16* __restrict__ yh, bf16* __restrict__ yl,
                     const float* __restrict__ sc, const float* __restrict__ bi) {
    int row = blockIdx.x;
    const float* xr = x + (size_t)row*WDIM;
    int tid = threadIdx.x;
    float v0 = xr[tid], v1 = xr[tid+256], v2 = xr[tid+512];
    float s  = v0+v1+v2;
    float sq = v0*v0 + v1*v1 + v2*v2;
    #pragma unroll
    for (int o = 16; o; o >>= 1) {
        s  += __shfl_xor_sync(0xffffffffu, s,  o);
        sq += __shfl_xor_sync(0xffffffffu, sq, o);
    }
    __shared__ float ss[8], sqs[8];
    __shared__ float smean, sinv;
    int wid = tid >> 5, lane = tid & 31;
    if (lane == 0) { ss[wid] = s; sqs[wid] = sq; }
    __syncthreads();
    if (tid == 0) {
        float S = 0.f, Q = 0.f;
        #pragma unroll
        for (int i = 0; i < 8; i++) { S += ss[i]; Q += sqs[i]; }
        float m  = S / (float)WDIM;
        float var = Q / (float)WDIM - m*m;
        smean = m;
        sinv  = rsqrtf(var + EPS);
    }
    __syncthreads();
    float m = smean, inv = sinv;
    size_t base = (size_t)row*WDIM;
    #pragma unroll
    for (int e = 0; e < 3; e++) {
        int c = tid + e*256;
        float vv = (e==0?v0:(e==1?v1:v2));
        float o = (vv - m)*inv*sc[c] + bi[c];
        if (y) y[base + c] = o;
        bf16 h, l; split1(o, h, l);
        yh[base + c] = h; yl[base + c] = l;
    }
}

// ---------------- split-bf16 tensor-core GEMM (ldmatrix + mma.sync) ----------------
// C[M,N] = A[M,K] * W, A given as hi/lo bf16 [M][K]; B = W^T hi/lo bf16 [N][K].
// 3 passes: Ah*Bh + Ah*Bl + Al*Bh, fp32 accum.
// CTA tile 128x128, BK=64, 3-stage cp.async pipeline, SW128 swizzle.
// SMEM per stage: Ahi,Alo,Bhi,Blo each 128x64 bf16 = 16KB -> 64KB; 3 stages = 192KB.
#define GSTAGES 3
#define GEMM_SMEM (GSTAGES*65536)

template<bool GELU, bool RES, bool SPLIT>
__global__ void __launch_bounds__(256, 1)
gemm_mma(const bf16* __restrict__ Ahi, const bf16* __restrict__ Alo,
         const bf16* __restrict__ Bhi, const bf16* __restrict__ Blo,
         const float* __restrict__ bias, const float* __restrict__ R,
         float* __restrict__ C, bf16* __restrict__ Chi, bf16* __restrict__ Clo,
         int M, int N, int K) {
    extern __shared__ __align__(1024) char smem[];
    const uint32_t sbase = smem_to_u32(smem);
    int tid = threadIdx.x;
    int wid = tid >> 5, lane = tid & 31;
    int bn = blockIdx.x * 128, bm = blockIdx.y * 128;

    const bf16* gsrc[4] = { Ahi + (size_t)bm*K, Alo + (size_t)bm*K,
                            Bhi + (size_t)bn*K, Blo + (size_t)bn*K };
    const int nch = K >> 6;

    // cp.async one stage (chunk ch into stage stg)
    auto issue = [&](int ch, int stg) {
        #pragma unroll
        for (int buf = 0; buf < 4; buf++) {
            uint32_t sdst = sbase + stg*65536 + buf*16384;
            const bf16* src = gsrc[buf] + ch*64;
            #pragma unroll
            for (int rr = 0; rr < 4; rr++) {
                int idx = rr*256 + tid;
                int row = idx >> 3, u = idx & 7;
                const void* g = src + (size_t)row*K + u*8;
                uint32_t off = (uint32_t)(row*128 + u*16);
                CP_ASYNC16(sdst + SWZ(off), g);
            }
        }
    };

    // warp tiling: 4 (M) x 2 (N) warps; warp tile 32x64
    int m0w = (wid >> 1) * 32, n0w = (wid & 1) * 64;
    int jj = lane >> 3, rr8 = lane & 7;
    int arow = m0w + (jj & 1)*8 + rr8;          // + mt*16
    int acol = (jj >> 1) * 8;                   // + kk*16
    int brow = n0w + (jj >> 1)*8 + rr8;         // + np*16
    int bcol = (jj & 1) * 8;                    // + kk*16

    float acc[2][8][4];
    #pragma unroll
    for (int mt = 0; mt < 2; mt++)
        #pragma unroll
        for (int nt = 0; nt < 8; nt++)
            #pragma unroll
            for (int r = 0; r < 4; r++) acc[mt][nt][r] = 0.f;

    issue(0, 0); CP_COMMIT();
    issue(1, 1); CP_COMMIT();

    for (int ch = 0; ch < nch; ch++) {
        if (ch + 2 < nch) issue(ch + 2, (ch + 2) % GSTAGES);
        CP_COMMIT();
        CP_WAIT2();
        __syncthreads();

        uint32_t sA = sbase + (ch % GSTAGES)*65536;
        #pragma unroll
        for (int kk = 0; kk < 4; kk++) {
            uint32_t ah[2][4], al[2][4];
            #pragma unroll
            for (int mt = 0; mt < 2; mt++) {
                uint32_t off = (uint32_t)((arow + mt*16)*128 + (kk*16 + acol)*2);
                uint32_t sw = SWZ(off);
                LDSM_X4(ah[mt], sA + sw);
                LDSM_X4(al[mt], sA + 16384 + sw);
            }
            uint32_t bh[4][4], bl[4][4];
            #pragma unroll
            for (int np = 0; np < 4; np++) {
                uint32_t off = (uint32_t)((brow + np*16)*128 + (kk*16 + bcol)*2);
                uint32_t sw = SWZ(off);
                LDSM_X4(bh[np], sA + 32768 + sw);
                LDSM_X4(bl[np], sA + 49152 + sw);
            }
            #pragma unroll
            for (int mt = 0; mt < 2; mt++)
                #pragma unroll
                for (int nt = 0; nt < 8; nt++) {
                    uint32_t bh0 = bh[nt>>1][(nt&1)*2], bh1 = bh[nt>>1][(nt&1)*2+1];
                    uint32_t bl0 = bl[nt>>1][(nt&1)*2], bl1 = bl[nt>>1][(nt&1)*2+1];
                    MMA16816(acc[mt][nt], ah[mt], bh0, bh1);
                    MMA16816(acc[mt][nt], ah[mt], bl0, bl1);
                    MMA16816(acc[mt][nt], al[mt], bh0, bh1);
                }
        }
        __syncthreads();
    }

    // epilogue
    int lr = lane >> 2, lc = (lane & 3) * 2;
    #pragma unroll
    for (int mt = 0; mt < 2; mt++) {
        #pragma unroll
        for (int nt = 0; nt < 8; nt++) {
            int col = bn + n0w + nt*8 + lc;
            float b0 = bias[col], b1 = bias[col+1];
            int r0 = bm + m0w + mt*16 + lr;
            #pragma unroll
            for (int half = 0; half < 2; half++) {
                int m = r0 + half*8;
                float v0 = acc[mt][nt][half*2]   + b0;
                float v1 = acc[mt][nt][half*2+1] + b1;
                if (GELU) { v0 = gelu_f(v0); v1 = gelu_f(v1); }
                if (SPLIT) {
                    bf16 h0, l0, h1, l1;
                    split1(v0, h0, l0); split1(v1, h1, l1);
                    size_t o = (size_t)m*N + col;
                    *(__nv_bfloat162*)(Chi + o) = __nv_bfloat162(h0, h1);
                    *(__nv_bfloat162*)(Clo + o) = __nv_bfloat162(l0, l1);
                } else {
                    size_t o = (size_t)m*N + col;
                    if (RES) {
                        float2 rv = *(const float2*)(R + o);
                        v0 += rv.x; v1 += rv.y;
                    }
                    *(float2*)(C + o) = make_float2(v0, v1);
                }
            }
        }
    }
}

// ---------------- attention: 16 queries per block, split-bf16 output ----------------
#define QT 16
__global__ void __launch_bounds__(256)
attn_k(const float* __restrict__ Q, const float* __restrict__ K,
       const float* __restrict__ V, bf16* __restrict__ Ohi, bf16* __restrict__ Olo) {
    __shared__ float sq[QT][HDIM];
    __shared__ float sp[QT][LTOK];
    __shared__ float sinv[QT];
    int b  = blockIdx.x;
    int qt = b % (LTOK/QT);
    int nh = b / (LTOK/QT);
    int hh = nh % NHEAD;
    int n  = nh / NHEAD;
    int q0 = qt * QT;
    int tid = threadIdx.x;

    {
        int qr = tid >> 4, d4 = tid & 15;
        *(float4*)&sq[qr][d4*4] =
            *(const float4*)(Q + ((size_t)(n*LTOK + q0 + qr)*NHEAD + hh)*HDIM + d4*4);
    }
    __syncthreads();

    for (int kc = 0; kc < 3; kc++) {
        int k = kc*256 + tid;
        if (k < LTOK) {
            const float4* Kp = (const float4*)(K + ((size_t)(n*LTOK + k)*NHEAD + hh)*HDIM);
            float acc[QT];
            #pragma unroll
            for (int q = 0; q < QT; q++) acc[q] = 0.f;
            #pragma unroll
            for (int d4 = 0; d4 < 16; d4++) {
                float4 kv = Kp[d4];
                #pragma unroll
                for (int q = 0; q < QT; q++) {
                    float4 qv = *(const float4*)&sq[q][d4*4];
                    acc[q] += qv.x*kv.x + qv.y*kv.y + qv.z*kv.z + qv.w*kv.w;
                }
            }
            #pragma unroll
            for (int q = 0; q < QT; q++) sp[q][k] = acc[q]*0.125f;
        }
    }
    __syncthreads();

    {
        int w = tid >> 5, lane = tid & 31;
        for (int rr = 0; rr < 2; rr++) {
            int q = w*2 + rr;
            float mx = -1e30f;
            for (int i = lane; i < LTOK; i += 32) mx = fmaxf(mx, sp[q][i]);
            #pragma unroll
            for (int o = 16; o; o >>= 1) mx = fmaxf(mx, __shfl_xor_sync(0xffffffffu, mx, o));
            float s = 0.f;
            for (int i = lane; i < LTOK; i += 32) {
                float e = __expf(sp[q][i] - mx);
                sp[q][i] = e;
                s += e;
            }
            #pragma unroll
            for (int o = 16; o; o >>= 1) s += __shfl_xor_sync(0xffffffffu, s, o);
            if (lane == 0) sinv[q] = 1.f / s;
        }
    }
    __syncthreads();

    int part = tid >> 6, d = tid & 63;
    float acc[QT];
    #pragma unroll
    for (int q = 0; q < QT; q++) acc[q] = 0.f;
    for (int k = part; k < LTOK; k += 4) {
        float v = V[((size_t)(n*LTOK + k)*NHEAD + hh)*HDIM + d];
        #pragma unroll
        for (int q = 0; q < QT; q++) acc[q] += sp[q][k]*v;
    }
    __syncthreads();
    float* red = &sp[0][0];
    #pragma unroll
    for (int q = 0; q < QT; q++) red[(part*QT + q)*64 + d] = acc[q];
    __syncthreads();
    #pragma unroll
    for (int i = 0; i < 4; i++) {
        int o = i*256 + tid;
        int q = o >> 6, dd = o & 63;
        float v = (red[q*64 + dd] + red[(QT+q)*64 + dd] +
                   red[(2*QT+q)*64 + dd] + red[(3*QT+q)*64 + dd]) * sinv[q];
        size_t oidx = ((size_t)(n*LTOK + q0 + q)*NHEAD + hh)*HDIM + dd;
        bf16 h, l; split1(v, h, l);
        Ohi[oidx] = h; Olo[oidx] = l;
    }
}

// ---------------- final mean over tokens ----------------
__global__ void mean_k(const float* __restrict__ y, float* __restrict__ out) {
    int c = blockIdx.x*256 + threadIdx.x;
    int n = blockIdx.y;
    if (c >= WDIM) return;
    float acc = 0.f;
    for (int l = 0; l < LTOK; l++)
        acc += y[(size_t)(n*LTOK + l)*WDIM + c];
    out[(size_t)n*WDIM + c] = acc * (1.f/(float)LTOK);
}

// ---------------- host orchestration ----------------
extern "C" void kernel_launch(void* const* d_in, const int* in_sizes, int n_in,
                              void* d_out, int out_size) {
    const float* image     = (const float*)d_in[0];
    const float* conv_ker  = (const float*)d_in[1];
    const float* conv_bias = (const float*)d_in[2];
    const float* ln1_scale = (const float*)d_in[3];
    const float* ln1_bias  = (const float*)d_in[4];
    const float* wq        = (const float*)d_in[5];
    const float* bq        = (const float*)d_in[6];
    const float* wk        = (const float*)d_in[7];
    const float* bk        = (const float*)d_in[8];
    const float* wv        = (const float*)d_in[9];
    const float* bv        = (const float*)d_in[10];
    const float* wo        = (const float*)d_in[11];
    const float* bo        = (const float*)d_in[12];
    const float* ln2_scale = (const float*)d_in[13];
    const float* ln2_bias  = (const float*)d_in[14];
    const float* w1        = (const float*)d_in[15];
    const float* b1        = (const float*)d_in[16];
    const float* w2        = (const float*)d_in[17];
    const float* b2        = (const float*)d_in[18];
    const float* lnf_scale = (const float*)d_in[19];
    const float* lnf_bias  = (const float*)d_in[20];
    float* out = (float*)d_out;

    float *x, *y, *q, *k, *v, *rope;
    bf16 *yh, *yl, *oh, *ol, *h1h, *h1l, *whi, *wlo;
    cudaGetSymbolAddress((void**)&x,    g_x);
    cudaGetSymbolAddress((void**)&y,    g_y);
    cudaGetSymbolAddress((void**)&q,    g_q);
    cudaGetSymbolAddress((void**)&k,    g_k);
    cudaGetSymbolAddress((void**)&v,    g_v);
    cudaGetSymbolAddress((void**)&rope, g_rope);
    cudaGetSymbolAddress((void**)&yh,   g_yh);
    cudaGetSymbolAddress((void**)&yl,   g_yl);
    cudaGetSymbolAddress((void**)&oh,   g_oh);
    cudaGetSymbolAddress((void**)&ol,   g_ol);
    cudaGetSymbolAddress((void**)&h1h,  g_h1h);
    cudaGetSymbolAddress((void**)&h1l,  g_h1l);
    cudaGetSymbolAddress((void**)&whi,  g_whi);
    cudaGetSymbolAddress((void**)&wlo,  g_wlo);

    cudaFuncSetAttribute(gemm_mma<false,false,false>, cudaFuncAttributeMaxDynamicSharedMemorySize, GEMM_SMEM);
    cudaFuncSetAttribute(gemm_mma<false,true, false>, cudaFuncAttributeMaxDynamicSharedMemorySize, GEMM_SMEM);
    cudaFuncSetAttribute(gemm_mma<true, false,true >, cudaFuncAttributeMaxDynamicSharedMemorySize, GEMM_SMEM);

    // ---- weight transpose + bf16 split ----
    dim3 tb(32, 8);
    {
        dim3 g(WDIM/32, WDIM/32);
        transcvt_k<<<g, tb>>>(conv_ker, whi, wlo, WDIM, WDIM);
    }
    for (int l = 0; l < DEPTH; l++) {
        size_t base = SZ_PROJ + (size_t)l*(4*SZ_PROJ + 2*SZ_MLP);
        dim3 gp(WDIM/32, WDIM/32);
        transcvt_k<<<gp, tb>>>(wq + (size_t)l*SZ_PROJ, whi + base,            wlo + base,            WDIM, WDIM);
        transcvt_k<<<gp, tb>>>(wk + (size_t)l*SZ_PROJ, whi + base + SZ_PROJ,  wlo + base + SZ_PROJ,  WDIM, WDIM);
        transcvt_k<<<gp, tb>>>(wv + (size_t)l*SZ_PROJ, whi + base + 2*SZ_PROJ,wlo + base + 2*SZ_PROJ,WDIM, WDIM);
        transcvt_k<<<gp, tb>>>(wo + (size_t)l*SZ_PROJ, whi + base + 3*SZ_PROJ,wlo + base + 3*SZ_PROJ,WDIM, WDIM);
        dim3 g1(MLPDIM/32, WDIM/32);
        transcvt_k<<<g1, tb>>>(w1 + (size_t)l*SZ_MLP, whi + base + 4*SZ_PROJ, wlo + base + 4*SZ_PROJ, WDIM, MLPDIM);
        dim3 g2(WDIM/32, MLPDIM/32);
        transcvt_k<<<g2, tb>>>(w2 + (size_t)l*SZ_MLP, whi + base + 4*SZ_PROJ + SZ_MLP, wlo + base + 4*SZ_PROJ + SZ_MLP, MLPDIM, WDIM);
    }

    rope_cache_k<<<(LTOK*16 + 255)/256, 256>>>(rope);

    // patch embed (im2col split reuses h1 buffers)
    im2col_k<<<(NROWS*WDIM + 255)/256, 256>>>(image, h1h, h1l);
    {
        dim3 g(WDIM/128, NROWS/128);
        gemm_mma<false,false,false><<<g, 256, GEMM_SMEM>>>(h1h, h1l, whi, wlo, conv_bias,
                                                           nullptr, x, nullptr, nullptr,
                                                           NROWS, WDIM, WDIM);
    }

    dim3 gProj(WDIM/128, NROWS/128);     // 6 x 36
    dim3 gMlp1(MLPDIM/128, NROWS/128);   // 24 x 36
    const int ropeTot = BATCH*LTOK*NHEAD*32;

    for (int l = 0; l < DEPTH; l++) {
        size_t base = SZ_PROJ + (size_t)l*(4*SZ_PROJ + 2*SZ_MLP);
        const bf16 *hq = whi + base,             *lq = wlo + base;
        const bf16 *hk = whi + base + SZ_PROJ,   *lk = wlo + base + SZ_PROJ;
        const bf16 *hv = whi + base + 2*SZ_PROJ, *lv = wlo + base + 2*SZ_PROJ;
        const bf16 *ho = whi + base + 3*SZ_PROJ, *lo = wlo + base + 3*SZ_PROJ;
        const bf16 *h1w= whi + base + 4*SZ_PROJ, *l1w= wlo + base + 4*SZ_PROJ;
        const bf16 *h2w= whi + base + 4*SZ_PROJ + SZ_MLP, *l2w = wlo + base + 4*SZ_PROJ + SZ_MLP;
        const float* bq_l = bq + (size_t)l*WDIM;
        const float* bk_l = bk + (size_t)l*WDIM;
        const float* bv_l = bv + (size_t)l*WDIM;
        const float* bo_l = bo + (size_t)l*WDIM;
        const float* b1_l = b1 + (size_t)l*MLPDIM;
        const float* b2_l = b2 + (size_t)l*WDIM;

        ln_k<<<NROWS, 256>>>(x, nullptr, yh, yl, ln1_scale + (size_t)l*WDIM, ln1_bias + (size_t)l*WDIM);

        gemm_mma<false,false,false><<<gProj, 256, GEMM_SMEM>>>(yh, yl, hq, lq, bq_l, nullptr, q, nullptr, nullptr, NROWS, WDIM, WDIM);
        gemm_mma<false,false,false><<<gProj, 256, GEMM_SMEM>>>(yh, yl, hk, lk, bk_l, nullptr, k, nullptr, nullptr, NROWS, WDIM, WDIM);
        gemm_mma<false,false,false><<<gProj, 256, GEMM_SMEM>>>(yh, yl, hv, lv, bv_l, nullptr, v, nullptr, nullptr, NROWS, WDIM, WDIM);

        rope_apply_k<<<(ropeTot + 255)/256, 256>>>(q, rope);
        rope_apply_k<<<(ropeTot + 255)/256, 256>>>(k, rope);

        attn_k<<<BATCH*NHEAD*(LTOK/QT), 256>>>(q, k, v, oh, ol);

        gemm_mma<false,true,false><<<gProj, 256, GEMM_SMEM>>>(oh, ol, ho, lo, bo_l, x, x, nullptr, nullptr, NROWS, WDIM, WDIM);

        ln_k<<<NROWS, 256>>>(x, nullptr, yh, yl, ln2_scale + (size_t)l*WDIM, ln2_bias + (size_t)l*WDIM);

        gemm_mma<true,false,true><<<gMlp1, 256, GEMM_SMEM>>>(yh, yl, h1w, l1w, b1_l, nullptr, nullptr, h1h, h1l, NROWS, MLPDIM, WDIM);
        gemm_mma<false,true,false><<<gProj, 256, GEMM_SMEM>>>(h1h, h1l, h2w, l2w, b2_l, x, x, nullptr, nullptr, NROWS, WDIM, MLPDIM);
    }

    ln_k<<<NROWS, 256>>>(x, y, yh, yl, lnf_scale, lnf_bias);
    {
        dim3 g((WDIM + 255)/256, BATCH);
        mean_k<<<g, 256>>>(y, out);
    }
}

// round 5
// speedup vs baseline: 5.9557x; 1.4297x over previous
#include <cuda_runtime.h>
#include <cuda_fp16.h>
#include <cstdint>
#include <cstddef>

// ---------------- problem constants ----------------
#define BATCH   8
#define IMG     384
#define CIN     3
#define PATCH   16
#define GRIDP   24          // IMG/PATCH
#define LTOK    576         // GRIDP*GRIDP
#define WDIM    768
#define DEPTH   4
#define NHEAD   12
#define HDIM    64
#define MLPDIM  3072
#define NROWS   (BATCH*LTOK)        // 4608
#define EPS     1e-6f

// ---------------- PTX helpers (plain sm_103 — NO tcgen05) ----------------
__device__ __forceinline__ uint32_t smem_to_u32(const void* smem_ptr) {
    uint32_t addr;
    asm("{ .reg .u64 tmp; cvta.to.shared.u64 tmp, %1; cvt.u32.u64 %0, tmp; }"
        : "=r"(addr) : "l"(smem_ptr));
    return addr;
}
#define CP_ASYNC16(dst, src) \
    asm volatile("cp.async.cg.shared.global [%0], [%1], 16;" :: "r"(dst), "l"(src) : "memory")
#define CP_COMMIT() asm volatile("cp.async.commit_group;" ::: "memory")
#define CP_WAIT3()  asm volatile("cp.async.wait_group 3;" ::: "memory")

#define LDSM_X4(r, addr) \
    asm volatile("ldmatrix.sync.aligned.m8n8.x4.shared.b16 {%0,%1,%2,%3}, [%4];" \
        : "=r"((r)[0]), "=r"((r)[1]), "=r"((r)[2]), "=r"((r)[3]) : "r"(addr))
#define LDSM_X4T(r, addr) \
    asm volatile("ldmatrix.sync.aligned.m8n8.x4.trans.shared.b16 {%0,%1,%2,%3}, [%4];" \
        : "=r"((r)[0]), "=r"((r)[1]), "=r"((r)[2]), "=r"((r)[3]) : "r"(addr))

#define MMA16816(d, a, b0, b1) \
    asm volatile("mma.sync.aligned.m16n8k16.row.col.f32.f16.f16.f32 " \
        "{%0,%1,%2,%3}, {%4,%5,%6,%7}, {%8,%9}, {%0,%1,%2,%3};" \
        : "+f"((d)[0]), "+f"((d)[1]), "+f"((d)[2]), "+f"((d)[3]) \
        : "r"((a)[0]), "r"((a)[1]), "r"((a)[2]), "r"((a)[3]), "r"(b0), "r"(b1))

#define SWZA(off) ((off) ^ (((off) >> 3) & 0x70))   // 128B rows (A tile)
#define SWZB(off) ((off) ^ (((off) >> 4) & 0x70))   // 256B rows (B tile)

// ---------------- scratch (static device globals; no allocations) ----------------
__device__ __align__(256) float g_x [NROWS*WDIM];
__device__ __align__(256) float g_y [NROWS*WDIM];
__device__ __align__(256) float g_q [NROWS*WDIM];
__device__ __align__(256) float g_k [NROWS*WDIM];
__device__ __align__(256) float g_v [NROWS*WDIM];
__device__ __align__(256) float g_rope[4*LTOK*16];

__device__ __align__(256) __half g_yh [NROWS*WDIM];
__device__ __align__(256) __half g_oh [NROWS*WDIM];
__device__ __align__(256) __half g_h1h[NROWS*MLPDIM];   // also im2col buffer

// weight buffer (fp16, natural [K,N] layout): [conv][wq x4][wk x4][wv x4][wo x4][w1 x4][w2 x4]
#define C0 589824                         // 768*768
#define WBUF_TOTAL (49*C0)                // 28,901,376
__device__ __align__(256) __half g_wh[WBUF_TOTAL];

// ---------------- small helpers ----------------
__device__ __forceinline__ float gelu_f(float x) {
    float x3 = x*x*x;
    return 0.5f*x*(1.f + tanhf(0.7978845608028654f*(x + 0.044715f*x3)));
}

// ---------------- weight convert: one flat kernel, fp32 -> fp16, vec4 ----------------
__global__ void wcvt_k(const float* __restrict__ conv, const float* __restrict__ wq,
                       const float* __restrict__ wk, const float* __restrict__ wv,
                       const float* __restrict__ wo, const float* __restrict__ w1,
                       const float* __restrict__ w2, __half* __restrict__ dst) {
    size_t i4 = ((size_t)blockIdx.x*256 + threadIdx.x) * 4;
    if (i4 >= (size_t)WBUF_TOTAL) return;
    const float* src;
    size_t off;
    if      (i4 <  (size_t)C0)     { src = conv; off = i4; }
    else if (i4 <  (size_t)5*C0)   { src = wq;   off = i4 - (size_t)C0; }
    else if (i4 <  (size_t)9*C0)   { src = wk;   off = i4 - (size_t)5*C0; }
    else if (i4 <  (size_t)13*C0)  { src = wv;   off = i4 - (size_t)9*C0; }
    else if (i4 <  (size_t)17*C0)  { src = wo;   off = i4 - (size_t)13*C0; }
    else if (i4 <  (size_t)33*C0)  { src = w1;   off = i4 - (size_t)17*C0; }
    else                           { src = w2;   off = i4 - (size_t)33*C0; }
    float4 v = *(const float4*)(src + off);
    __half2* d = (__half2*)(dst + i4);
    d[0] = __floats2half2_rn(v.x, v.y);
    d[1] = __floats2half2_rn(v.z, v.w);
}

// ---------------- im2col (fp16 out) ----------------
__global__ void im2col_k(const float* __restrict__ img, __half* __restrict__ oh) {
    int idx = blockIdx.x*256 + threadIdx.x;
    if (idx >= NROWS*WDIM) return;
    int t  = idx % WDIM;
    int nl = idx / WDIM;
    int l  = nl % LTOK;
    int n  = nl / LTOK;
    int ci = t % 3;
    int ij = t / 3;
    int j  = ij % PATCH;
    int i  = ij / PATCH;
    int px = l % GRIDP, py = l / GRIDP;
    float v = img[ (((size_t)n*IMG + (py*PATCH+i))*IMG + (px*PATCH+j))*CIN + ci ];
    oh[idx] = __float2half_rn(v);
}

// ---------------- rope cache / apply ----------------
__global__ void rope_cache_k(float* __restrict__ cache) {
    int idx = blockIdx.x*256 + threadIdx.x;
    if (idx >= LTOK*16) return;
    int f = idx % 16, l = idx / 16;
    float freq = (float)f / (15.f + 1e-9f);
    float inv  = powf(10000.f, -freq);
    float u = ((float)(l % GRIDP) + 0.5f) / (float)GRIDP;
    float v = ((float)(l / GRIDP) + 0.5f) / (float)GRIDP;
    float ax = u*inv, ay = v*inv;
    cache[0*LTOK*16 + idx] = cosf(ax);
    cache[1*LTOK*16 + idx] = sinf(ax);
    cache[2*LTOK*16 + idx] = cosf(ay);
    cache[3*LTOK*16 + idx] = sinf(ay);
}
// blockIdx.y: 0 -> q, 1 -> k
__global__ void rope_apply_k(float* __restrict__ qp, float* __restrict__ kp,
                             const float* __restrict__ cache) {
    int idx = blockIdx.x*256 + threadIdx.x;
    const int TOT = BATCH*LTOK*NHEAD*32;
    if (idx >= TOT) return;
    float* dst = blockIdx.y ? kp : qp;
    int p  = idx % 32;
    int h  = (idx/32) % NHEAD;
    int l  = (idx/(32*NHEAD)) % LTOK;
    int n  = idx/(32*NHEAD*LTOK);
    float c, s;
    if (p < 16) { c = cache[0*LTOK*16 + l*16 + p];    s = cache[1*LTOK*16 + l*16 + p]; }
    else        { c = cache[2*LTOK*16 + l*16 + p-16]; s = cache[3*LTOK*16 + l*16 + p-16]; }
    float* ptr = dst + (((size_t)(n*LTOK+l)*NHEAD + h)*HDIM) + 2*p;
    float x = ptr[0], y = ptr[1];
    ptr[0] = x*c - y*s;
    ptr[1] = x*s + y*c;
}

// ---------------- layernorm (row = 768): fp16 out (+ optional fp32 out) ----------------
__global__ void ln_k(const float* __restrict__ x, float* __restrict__ y,
                     __half* __restrict__ yh,
                     const float* __restrict__ sc, const float* __restrict__ bi) {
    int row = blockIdx.x;
    const float* xr = x + (size_t)row*WDIM;
    int tid = threadIdx.x;
    float v0 = xr[tid], v1 = xr[tid+256], v2 = xr[tid+512];
    float s  = v0+v1+v2;
    float sq = v0*v0 + v1*v1 + v2*v2;
    #pragma unroll
    for (int o = 16; o; o >>= 1) {
        s  += __shfl_xor_sync(0xffffffffu, s,  o);
        sq += __shfl_xor_sync(0xffffffffu, sq, o);
    }
    __shared__ float ss[8], sqs[8];
    __shared__ float smean, sinv;
    int wid = tid >> 5, lane = tid & 31;
    if (lane == 0) { ss[wid] = s; sqs[wid] = sq; }
    __syncthreads();
    if (tid == 0) {
        float S = 0.f, Q = 0.f;
        #pragma unroll
        for (int i = 0; i < 8; i++) { S += ss[i]; Q += sqs[i]; }
        float m  = S / (float)WDIM;
        float var = Q / (float)WDIM - m*m;
        smean = m;
        sinv  = rsqrtf(var + EPS);
    }
    __syncthreads();
    float m = smean, inv = sinv;
    size_t base = (size_t)row*WDIM;
    #pragma unroll
    for (int e = 0; e < 3; e++) {
        int c = tid + e*256;
        float vv = (e==0?v0:(e==1?v1:v2));
        float o = (vv - m)*inv*sc[c] + bi[c];
        if (y) y[base + c] = o;
        yh[base + c] = __float2half_rn(o);
    }
}

// ---------------- fp16 tensor-core GEMM (single pass, fp32 accum) ----------------
// C[M,N] = A[M,K](fp16) * B[K,N](fp16, natural layout, ldmatrix.trans) + bias
// CTA tile 128x128, BK=64, 4-stage cp.async pipeline.
// SMEM per stage: A 128x64 (16KB, SWZA) + B 64x128 (16KB, SWZB) = 32KB; 4 stages = 128KB.
#define GSTAGES 4
#define GEMM_SMEM (GSTAGES*32768)

template<bool GELU, bool RES, bool HOUT>
__global__ void __launch_bounds__(256, 1)
gemm_mma(const __half* __restrict__ A, const __half* __restrict__ B,
         const float* __restrict__ bias, const float* __restrict__ R,
         float* __restrict__ C, __half* __restrict__ Ch,
         int M, int N, int K) {
    extern __shared__ __align__(1024) char smem[];
    const uint32_t sbase = smem_to_u32(smem);
    int tid = threadIdx.x;
    int wid = tid >> 5, lane = tid & 31;
    int bn = blockIdx.x * 128, bm = blockIdx.y * 128;

    const __half* Aptr = A + (size_t)bm*K;
    const int nch = K >> 6;

    auto issue = [&](int ch, int stg) {
        uint32_t sA = sbase + stg*32768;
        uint32_t sB = sA + 16384;
        const __half* srcA = Aptr + ch*64;
        #pragma unroll
        for (int rr = 0; rr < 4; rr++) {
            int idx = rr*256 + tid;
            int row = idx >> 3, u = idx & 7;
            const void* g = srcA + (size_t)row*K + u*8;
            uint32_t off = (uint32_t)(row*128 + u*16);
            CP_ASYNC16(sA + SWZA(off), g);
        }
        const __half* srcB = B + (size_t)(ch*64)*N + bn;
        #pragma unroll
        for (int rr = 0; rr < 4; rr++) {
            int idx = rr*256 + tid;
            int row = idx >> 4, u = idx & 15;
            const void* g = srcB + (size_t)row*N + u*8;
            uint32_t off = (uint32_t)(row*256 + u*16);
            CP_ASYNC16(sB + SWZB(off), g);
        }
    };

    // warp tiling: 4 (M) x 2 (N) warps; warp tile 32x64
    int m0w = (wid >> 1) * 32, n0w = (wid & 1) * 64;
    int jj = lane >> 3, rr8 = lane & 7;
    int arow = m0w + (jj & 1)*8 + rr8;
    int acol = (jj >> 1) * 8;
    int btrow = lane & 15;                     // + kk*16
    int btcol = n0w + ((lane >> 4) << 3);      // + np*16

    float acc[2][8][4];
    #pragma unroll
    for (int mt = 0; mt < 2; mt++)
        #pragma unroll
        for (int nt = 0; nt < 8; nt++)
            #pragma unroll
            for (int r = 0; r < 4; r++) acc[mt][nt][r] = 0.f;

    issue(0, 0); CP_COMMIT();
    issue(1, 1); CP_COMMIT();
    issue(2, 2); CP_COMMIT();

    for (int ch = 0; ch < nch; ch++) {
        if (ch + 3 < nch) issue(ch + 3, (ch + 3) & (GSTAGES-1));
        CP_COMMIT();
        CP_WAIT3();
        __syncthreads();

        uint32_t sA = sbase + (ch & (GSTAGES-1))*32768;
        uint32_t sB = sA + 16384;
        #pragma unroll
        for (int kk = 0; kk < 4; kk++) {
            uint32_t a[2][4];
            #pragma unroll
            for (int mt = 0; mt < 2; mt++) {
                uint32_t off = (uint32_t)((arow + mt*16)*128 + (kk*16 + acol)*2);
                LDSM_X4(a[mt], sA + SWZA(off));
            }
            uint32_t bt[4][4];
            #pragma unroll
            for (int np = 0; np < 4; np++) {
                uint32_t off = (uint32_t)((kk*16 + btrow)*256 + (btcol + np*16)*2);
                LDSM_X4T(bt[np], sB + SWZB(off));
            }
            #pragma unroll
            for (int mt = 0; mt < 2; mt++)
                #pragma unroll
                for (int nt = 0; nt < 8; nt++)
                    MMA16816(acc[mt][nt], a[mt], bt[nt>>1][(nt&1)*2], bt[nt>>1][(nt&1)*2+1]);
        }
        __syncthreads();
    }

    // epilogue
    int lr = lane >> 2, lc = (lane & 3) * 2;
    #pragma unroll
    for (int mt = 0; mt < 2; mt++) {
        #pragma unroll
        for (int nt = 0; nt < 8; nt++) {
            int col = bn + n0w + nt*8 + lc;
            float b0 = bias[col], b1 = bias[col+1];
            int r0 = bm + m0w + mt*16 + lr;
            #pragma unroll
            for (int half = 0; half < 2; half++) {
                int m = r0 + half*8;
                float v0 = acc[mt][nt][half*2]   + b0;
                float v1 = acc[mt][nt][half*2+1] + b1;
                if (GELU) { v0 = gelu_f(v0); v1 = gelu_f(v1); }
                size_t o = (size_t)m*N + col;
                if (HOUT) {
                    *(__half2*)(Ch + o) = __floats2half2_rn(v0, v1);
                } else {
                    if (RES) {
                        float2 rv = *(const float2*)(R + o);
                        v0 += rv.x; v1 += rv.y;
                    }
                    *(float2*)(C + o) = make_float2(v0, v1);
                }
            }
        }
    }
}

// ---------------- attention: 16 queries per block, fp16 output ----------------
#define QT 16
__global__ void __launch_bounds__(256)
attn_k(const float* __restrict__ Q, const float* __restrict__ K,
       const float* __restrict__ V, __half* __restrict__ Oh) {
    __shared__ float sq[QT][HDIM];
    __shared__ float sp[QT][LTOK];
    __shared__ float sinv[QT];
    int b  = blockIdx.x;
    int qt = b % (LTOK/QT);
    int nh = b / (LTOK/QT);
    int hh = nh % NHEAD;
    int n  = nh / NHEAD;
    int q0 = qt * QT;
    int tid = threadIdx.x;

    {
        int qr = tid >> 4, d4 = tid & 15;
        *(float4*)&sq[qr][d4*4] =
            *(const float4*)(Q + ((size_t)(n*LTOK + q0 + qr)*NHEAD + hh)*HDIM + d4*4);
    }
    __syncthreads();

    for (int kc = 0; kc < 3; kc++) {
        int k = kc*256 + tid;
        if (k < LTOK) {
            const float4* Kp = (const float4*)(K + ((size_t)(n*LTOK + k)*NHEAD + hh)*HDIM);
            float acc[QT];
            #pragma unroll
            for (int q = 0; q < QT; q++) acc[q] = 0.f;
            #pragma unroll
            for (int d4 = 0; d4 < 16; d4++) {
                float4 kv = Kp[d4];
                #pragma unroll
                for (int q = 0; q < QT; q++) {
                    float4 qv = *(const float4*)&sq[q][d4*4];
                    acc[q] += qv.x*kv.x + qv.y*kv.y + qv.z*kv.z + qv.w*kv.w;
                }
            }
            #pragma unroll
            for (int q = 0; q < QT; q++) sp[q][k] = acc[q]*0.125f;
        }
    }
    __syncthreads();

    {
        int w = tid >> 5, lane = tid & 31;
        for (int rr = 0; rr < 2; rr++) {
            int q = w*2 + rr;
            float mx = -1e30f;
            for (int i = lane; i < LTOK; i += 32) mx = fmaxf(mx, sp[q][i]);
            #pragma unroll
            for (int o = 16; o; o >>= 1) mx = fmaxf(mx, __shfl_xor_sync(0xffffffffu, mx, o));
            float s = 0.f;
            for (int i = lane; i < LTOK; i += 32) {
                float e = __expf(sp[q][i] - mx);
                sp[q][i] = e;
                s += e;
            }
            #pragma unroll
            for (int o = 16; o; o >>= 1) s += __shfl_xor_sync(0xffffffffu, s, o);
            if (lane == 0) sinv[q] = 1.f / s;
        }
    }
    __syncthreads();

    int part = tid >> 6, d = tid & 63;
    float acc[QT];
    #pragma unroll
    for (int q = 0; q < QT; q++) acc[q] = 0.f;
    for (int k = part; k < LTOK; k += 4) {
        float v = V[((size_t)(n*LTOK + k)*NHEAD + hh)*HDIM + d];
        #pragma unroll
        for (int q = 0; q < QT; q++) acc[q] += sp[q][k]*v;
    }
    __syncthreads();
    float* red = &sp[0][0];
    #pragma unroll
    for (int q = 0; q < QT; q++) red[(part*QT + q)*64 + d] = acc[q];
    __syncthreads();
    #pragma unroll
    for (int i = 0; i < 4; i++) {
        int o = i*256 + tid;
        int q = o >> 6, dd = o & 63;
        float v = (red[q*64 + dd] + red[(QT+q)*64 + dd] +
                   red[(2*QT+q)*64 + dd] + red[(3*QT+q)*64 + dd]) * sinv[q];
        Oh[((size_t)(n*LTOK + q0 + q)*NHEAD + hh)*HDIM + dd] = __float2half_rn(v);
    }
}

// ---------------- final mean over tokens ----------------
__global__ void mean_k(const float* __restrict__ y, float* __restrict__ out) {
    int c = blockIdx.x*256 + threadIdx.x;
    int n = blockIdx.y;
    if (c >= WDIM) return;
    float acc = 0.f;
    for (int l = 0; l < LTOK; l++)
        acc += y[(size_t)(n*LTOK + l)*WDIM + c];
    out[(size_t)n*WDIM + c] = acc * (1.f/(float)LTOK);
}

// ---------------- host orchestration ----------------
extern "C" void kernel_launch(void* const* d_in, const int* in_sizes, int n_in,
                              void* d_out, int out_size) {
    const float* image     = (const float*)d_in[0];
    const float* conv_ker  = (const float*)d_in[1];
    const float* conv_bias = (const float*)d_in[2];
    const float* ln1_scale = (const float*)d_in[3];
    const float* ln1_bias  = (const float*)d_in[4];
    const float* wq        = (const float*)d_in[5];
    const float* bq        = (const float*)d_in[6];
    const float* wk        = (const float*)d_in[7];
    const float* bk        = (const float*)d_in[8];
    const float* wv        = (const float*)d_in[9];
    const float* bv        = (const float*)d_in[10];
    const float* wo        = (const float*)d_in[11];
    const float* bo        = (const float*)d_in[12];
    const float* ln2_scale = (const float*)d_in[13];
    const float* ln2_bias  = (const float*)d_in[14];
    const float* w1        = (const float*)d_in[15];
    const float* b1        = (const float*)d_in[16];
    const float* w2        = (const float*)d_in[17];
    const float* b2        = (const float*)d_in[18];
    const float* lnf_scale = (const float*)d_in[19];
    const float* lnf_bias  = (const float*)d_in[20];
    float* out = (float*)d_out;

    float *x, *y, *q, *k, *v, *rope;
    __half *yh, *oh, *h1h, *wh;
    cudaGetSymbolAddress((void**)&x,    g_x);
    cudaGetSymbolAddress((void**)&y,    g_y);
    cudaGetSymbolAddress((void**)&q,    g_q);
    cudaGetSymbolAddress((void**)&k,    g_k);
    cudaGetSymbolAddress((void**)&v,    g_v);
    cudaGetSymbolAddress((void**)&rope, g_rope);
    cudaGetSymbolAddress((void**)&yh,   g_yh);
    cudaGetSymbolAddress((void**)&oh,   g_oh);
    cudaGetSymbolAddress((void**)&h1h,  g_h1h);
    cudaGetSymbolAddress((void**)&wh,   g_wh);

    cudaFuncSetAttribute(gemm_mma<false,false,false>, cudaFuncAttributeMaxDynamicSharedMemorySize, GEMM_SMEM);
    cudaFuncSetAttribute(gemm_mma<false,true, false>, cudaFuncAttributeMaxDynamicSharedMemorySize, GEMM_SMEM);
    cudaFuncSetAttribute(gemm_mma<true, false,true >, cudaFuncAttributeMaxDynamicSharedMemorySize, GEMM_SMEM);

    // weight pointers inside g_wh (all natural [K,N], fp16)
    __half* w_conv = wh;
    __half* w_q    = wh + (size_t)1*C0;
    __half* w_k    = wh + (size_t)5*C0;
    __half* w_v    = wh + (size_t)9*C0;
    __half* w_o    = wh + (size_t)13*C0;
    __half* w_1    = wh + (size_t)17*C0;
    __half* w_2    = wh + (size_t)33*C0;

    // one flat weight-convert launch
    {
        size_t nv4 = (size_t)WBUF_TOTAL / 4;
        wcvt_k<<<(unsigned)((nv4 + 255)/256), 256>>>(conv_ker, wq, wk, wv, wo, w1, w2, wh);
    }

    rope_cache_k<<<(LTOK*16 + 255)/256, 256>>>(rope);

    // patch embed
    im2col_k<<<(NROWS*WDIM + 255)/256, 256>>>(image, h1h);
    {
        dim3 g(WDIM/128, NROWS/128);
        gemm_mma<false,false,false><<<g, 256, GEMM_SMEM>>>(h1h, w_conv, conv_bias,
                                                           nullptr, x, nullptr,
                                                           NROWS, WDIM, WDIM);
    }

    dim3 gProj(WDIM/128, NROWS/128);     // 6 x 36
    dim3 gMlp1(MLPDIM/128, NROWS/128);   // 24 x 36
    const int ropeTot = BATCH*LTOK*NHEAD*32;
    dim3 gRope((ropeTot + 255)/256, 2);

    for (int l = 0; l < DEPTH; l++) {
        const __half* wq_l = w_q + (size_t)l*C0;
        const __half* wk_l = w_k + (size_t)l*C0;
        const __half* wv_l = w_v + (size_t)l*C0;
        const __half* wo_l = w_o + (size_t)l*C0;
        const __half* w1_l = w_1 + (size_t)l*4*C0;
        const __half* w2_l = w_2 + (size_t)l*4*C0;
        const float* bq_l = bq + (size_t)l*WDIM;
        const float* bk_l = bk + (size_t)l*WDIM;
        const float* bv_l = bv + (size_t)l*WDIM;
        const float* bo_l = bo + (size_t)l*WDIM;
        const float* b1_l = b1 + (size_t)l*MLPDIM;
        const float* b2_l = b2 + (size_t)l*WDIM;

        ln_k<<<NROWS, 256>>>(x, nullptr, yh, ln1_scale + (size_t)l*WDIM, ln1_bias + (size_t)l*WDIM);

        gemm_mma<false,false,false><<<gProj, 256, GEMM_SMEM>>>(yh, wq_l, bq_l, nullptr, q, nullptr, NROWS, WDIM, WDIM);
        gemm_mma<false,false,false><<<gProj, 256, GEMM_SMEM>>>(yh, wk_l, bk_l, nullptr, k, nullptr, NROWS, WDIM, WDIM);
        gemm_mma<false,false,false><<<gProj, 256, GEMM_SMEM>>>(yh, wv_l, bv_l, nullptr, v, nullptr, NROWS, WDIM, WDIM);

        rope_apply_k<<<gRope, 256>>>(q, k, rope);

        attn_k<<<BATCH*NHEAD*(LTOK/QT), 256>>>(q, k, v, oh);

        gemm_mma<false,true,false><<<gProj, 256, GEMM_SMEM>>>(oh, wo_l, bo_l, x, x, nullptr, NROWS, WDIM, WDIM);

        ln_k<<<NROWS, 256>>>(x, nullptr, yh, ln2_scale + (size_t)l*WDIM, ln2_bias + (size_t)l*WDIM);

        gemm_mma<true,false,true><<<gMlp1, 256, GEMM_SMEM>>>(yh, w1_l, b1_l, nullptr, nullptr, h1h, NROWS, MLPDIM, WDIM);
        gemm_mma<false,true,false><<<gProj, 256, GEMM_SMEM>>>(h1h, w2_l, b2_l, x, x, nullptr, NROWS, WDIM, MLPDIM);
    }

    ln_k<<<NROWS, 256>>>(x, y, yh, lnf_scale, lnf_bias);
    {
        dim3 g((WDIM + 255)/256, BATCH);
        mean_k<<<g, 256>>>(y, out);
    }
}

// round 6
// speedup vs baseline: 11.1086x; 1.8652x over previous
#include <cuda_runtime.h>
#include <cuda_fp16.h>
#include <cstdint>
#include <cstddef>

// ---------------- problem constants ----------------
#define BATCH   8
#define IMG     384
#define CIN     3
#define PATCH   16
#define GRIDP   24
#define LTOK    576
#define WDIM    768
#define DEPTH   4
#define NHEAD   12
#define HDIM    64
#define MLPDIM  3072
#define NROWS   (BATCH*LTOK)
#define EPS     1e-6f
#define QKVN    (3*WDIM)            // 2304

// ---------------- PTX helpers ----------------
__device__ __forceinline__ uint32_t smem_to_u32(const void* smem_ptr) {
    uint32_t addr;
    asm("{ .reg .u64 tmp; cvta.to.shared.u64 tmp, %1; cvt.u32.u64 %0, tmp; }"
        : "=r"(addr) : "l"(smem_ptr));
    return addr;
}
#define CP_ASYNC16(dst, src) \
    asm volatile("cp.async.cg.shared.global [%0], [%1], 16;" :: "r"(dst), "l"(src) : "memory")
#define CP_COMMIT() asm volatile("cp.async.commit_group;" ::: "memory")
#define CP_WAIT3()  asm volatile("cp.async.wait_group 3;" ::: "memory")
#define CP_WAIT1()  asm volatile("cp.async.wait_group 1;" ::: "memory")

#define LDSM_X4(r, addr) \
    asm volatile("ldmatrix.sync.aligned.m8n8.x4.shared.b16 {%0,%1,%2,%3}, [%4];" \
        : "=r"((r)[0]), "=r"((r)[1]), "=r"((r)[2]), "=r"((r)[3]) : "r"(addr))
#define LDSM_X4T(r, addr) \
    asm volatile("ldmatrix.sync.aligned.m8n8.x4.trans.shared.b16 {%0,%1,%2,%3}, [%4];" \
        : "=r"((r)[0]), "=r"((r)[1]), "=r"((r)[2]), "=r"((r)[3]) : "r"(addr))

#define MMA16816(d, a, b0, b1) \
    asm volatile("mma.sync.aligned.m16n8k16.row.col.f32.f16.f16.f32 " \
        "{%0,%1,%2,%3}, {%4,%5,%6,%7}, {%8,%9}, {%0,%1,%2,%3};" \
        : "+f"((d)[0]), "+f"((d)[1]), "+f"((d)[2]), "+f"((d)[3]) \
        : "r"((a)[0]), "r"((a)[1]), "r"((a)[2]), "r"((a)[3]), "r"(b0), "r"(b1))

#define SWZA(off) ((off) ^ (((off) >> 3) & 0x70))   // 128B rows
#define SWZB(off) ((off) ^ (((off) >> 4) & 0x70))   // 256B rows

// ---------------- scratch ----------------
__device__ __align__(256) float g_x   [NROWS*WDIM];
__device__ __align__(256) float g_y   [NROWS*WDIM];
__device__ __align__(256) float g_qkv [NROWS*QKVN];
__device__ __align__(256) float g_rope[4*LTOK*16];
__device__ __align__(256) float g_bqkv[DEPTH*QKVN];

__device__ __align__(256) __half g_yh [NROWS*WDIM];
__device__ __align__(256) __half g_oh [NROWS*WDIM];
__device__ __align__(256) __half g_qh [NROWS*WDIM];   // head-major, pre-scaled
__device__ __align__(256) __half g_kh [NROWS*WDIM];   // head-major
__device__ __align__(256) __half g_vh [NROWS*WDIM];   // head-major
__device__ __align__(256) __half g_h1h[NROWS*MLPDIM];

#define C0 589824
__device__ __align__(256) __half g_wh  [37*C0];      // [conv][wo x4][w1 x4][w2 x4]
__device__ __align__(256) __half g_wqkv[12*C0];      // [l][768][2304]

// ---------------- small helpers ----------------
__device__ __forceinline__ float gelu_f(float x) {
    float x3 = x*x*x;
    return 0.5f*x*(1.f + tanhf(0.7978845608028654f*(x + 0.044715f*x3)));
}

// ---------------- weight convert (conv, wo, w1, w2) ----------------
__global__ void wcvt_k(const float* __restrict__ conv, const float* __restrict__ wo,
                       const float* __restrict__ w1, const float* __restrict__ w2,
                       __half* __restrict__ dst) {
    size_t i4 = ((size_t)blockIdx.x*256 + threadIdx.x) * 4;
    if (i4 >= (size_t)37*C0) return;
    const float* src; size_t off;
    if      (i4 < (size_t)C0)    { src = conv; off = i4; }
    else if (i4 < (size_t)5*C0)  { src = wo;   off = i4 - (size_t)C0; }
    else if (i4 < (size_t)21*C0) { src = w1;   off = i4 - (size_t)5*C0; }
    else                         { src = w2;   off = i4 - (size_t)21*C0; }
    float4 v = *(const float4*)(src + off);
    __half2* d = (__half2*)(dst + i4);
    d[0] = __floats2half2_rn(v.x, v.y);
    d[1] = __floats2half2_rn(v.z, v.w);
}

// ---------------- qkv weight interleave: [l][k][2304] ----------------
__global__ void wqkvcvt_k(const float* __restrict__ wq, const float* __restrict__ wk,
                          const float* __restrict__ wv, __half* __restrict__ dst) {
    size_t i4 = ((size_t)blockIdx.x*256 + threadIdx.x) * 4;
    if (i4 >= (size_t)12*C0) return;
    size_t l  = i4 / ((size_t)WDIM*QKVN);
    size_t r  = i4 % ((size_t)WDIM*QKVN);
    size_t k  = r / QKVN;
    size_t j  = r % QKVN;
    size_t blk = j / WDIM;
    const float* src = (blk == 0) ? wq : (blk == 1) ? wk : wv;
    float4 v = *(const float4*)(src + l*(size_t)C0 + k*WDIM + (j - blk*WDIM));
    __half2* d = (__half2*)(dst + i4);
    d[0] = __floats2half2_rn(v.x, v.y);
    d[1] = __floats2half2_rn(v.z, v.w);
}

__global__ void bcat_k(const float* __restrict__ bq, const float* __restrict__ bk,
                       const float* __restrict__ bv, float* __restrict__ dst) {
    int idx = blockIdx.x*256 + threadIdx.x;
    if (idx >= DEPTH*QKVN) return;
    int l = idx / QKVN, j = idx % QKVN;
    int blk = j / WDIM;
    const float* src = (blk == 0) ? bq : (blk == 1) ? bk : bv;
    dst[idx] = src[l*WDIM + (j - blk*WDIM)];
}

// ---------------- im2col (fp16) ----------------
__global__ void im2col_k(const float* __restrict__ img, __half* __restrict__ oh) {
    int idx = blockIdx.x*256 + threadIdx.x;
    if (idx >= NROWS*WDIM) return;
    int t  = idx % WDIM;
    int nl = idx / WDIM;
    int l  = nl % LTOK;
    int n  = nl / LTOK;
    int ci = t % 3;
    int ij = t / 3;
    int j  = ij % PATCH;
    int i  = ij / PATCH;
    int px = l % GRIDP, py = l / GRIDP;
    float v = img[ (((size_t)n*IMG + (py*PATCH+i))*IMG + (px*PATCH+j))*CIN + ci ];
    oh[idx] = __float2half_rn(v);
}

// ---------------- rope cache ----------------
__global__ void rope_cache_k(float* __restrict__ cache) {
    int idx = blockIdx.x*256 + threadIdx.x;
    if (idx >= LTOK*16) return;
    int f = idx % 16, l = idx / 16;
    float freq = (float)f / (15.f + 1e-9f);
    float inv  = powf(10000.f, -freq);
    float u = ((float)(l % GRIDP) + 0.5f) / (float)GRIDP;
    float v = ((float)(l / GRIDP) + 0.5f) / (float)GRIDP;
    float ax = u*inv, ay = v*inv;
    cache[0*LTOK*16 + idx] = cosf(ax);
    cache[1*LTOK*16 + idx] = sinf(ax);
    cache[2*LTOK*16 + idx] = cosf(ay);
    cache[3*LTOK*16 + idx] = sinf(ay);
}

// ---------------- qkv -> head-major fp16 (rope on q,k; q scaled by 1/8) ----------------
// grid.y: 0=q (rope+scale), 1=k (rope), 2=v (plain)
__global__ void qkvcvt_k(const float* __restrict__ qkv, const float* __restrict__ cache,
                         __half* __restrict__ qh, __half* __restrict__ kh,
                         __half* __restrict__ vh) {
    int idx = blockIdx.x*256 + threadIdx.x;
    const int TOT = BATCH*LTOK*NHEAD*32;
    if (idx >= TOT) return;
    int p  = idx & 31;
    int h  = (idx >> 5) % NHEAD;
    int l  = (idx >> 5) / NHEAD % LTOK;
    int n  = (idx >> 5) / (NHEAD*LTOK);
    size_t srow = (size_t)(n*LTOK + l)*QKVN;
    size_t dsto = ((size_t)(n*NHEAD + h)*LTOK + l)*HDIM + 2*p;
    int plane = blockIdx.y;
    if (plane == 2) {
        float v0 = qkv[srow + 2*WDIM + h*HDIM + 2*p];
        float v1 = qkv[srow + 2*WDIM + h*HDIM + 2*p + 1];
        *(__half2*)(vh + dsto) = __floats2half2_rn(v0, v1);
    } else {
        float c, s;
        if (p < 16) { c = cache[0*LTOK*16 + l*16 + p];    s = cache[1*LTOK*16 + l*16 + p]; }
        else        { c = cache[2*LTOK*16 + l*16 + p-16]; s = cache[3*LTOK*16 + l*16 + p-16]; }
        size_t so = srow + (plane ? WDIM : 0) + h*HDIM + 2*p;
        float x = qkv[so], y = qkv[so + 1];
        float rx = x*c - y*s, ry = x*s + y*c;
        if (plane == 0) { rx *= 0.125f; ry *= 0.125f; *(__half2*)(qh + dsto) = __floats2half2_rn(rx, ry); }
        else            { *(__half2*)(kh + dsto) = __floats2half2_rn(rx, ry); }
    }
}

// ---------------- layernorm ----------------
__global__ void ln_k(const float* __restrict__ x, float* __restrict__ y,
                     __half* __restrict__ yh,
                     const float* __restrict__ sc, const float* __restrict__ bi) {
    int row = blockIdx.x;
    const float* xr = x + (size_t)row*WDIM;
    int tid = threadIdx.x;
    float v0 = xr[tid], v1 = xr[tid+256], v2 = xr[tid+512];
    float s  = v0+v1+v2;
    float sq = v0*v0 + v1*v1 + v2*v2;
    #pragma unroll
    for (int o = 16; o; o >>= 1) {
        s  += __shfl_xor_sync(0xffffffffu, s,  o);
        sq += __shfl_xor_sync(0xffffffffu, sq, o);
    }
    __shared__ float ss[8], sqs[8];
    __shared__ float smean, sinv;
    int wid = tid >> 5, lane = tid & 31;
    if (lane == 0) { ss[wid] = s; sqs[wid] = sq; }
    __syncthreads();
    if (tid == 0) {
        float S = 0.f, Q = 0.f;
        #pragma unroll
        for (int i = 0; i < 8; i++) { S += ss[i]; Q += sqs[i]; }
        float m  = S / (float)WDIM;
        float var = Q / (float)WDIM - m*m;
        smean = m;
        sinv  = rsqrtf(var + EPS);
    }
    __syncthreads();
    float m = smean, inv = sinv;
    size_t base = (size_t)row*WDIM;
    #pragma unroll
    for (int e = 0; e < 3; e++) {
        int c = tid + e*256;
        float vv = (e==0?v0:(e==1?v1:v2));
        float o = (vv - m)*inv*sc[c] + bi[c];
        if (y) y[base + c] = o;
        yh[base + c] = __float2half_rn(o);
    }
}

// ---------------- fp16 tensor-core GEMM (same core as R5) ----------------
#define GSTAGES 4
#define GEMM_SMEM (GSTAGES*32768)

template<bool GELU, bool RES, bool HOUT>
__global__ void __launch_bounds__(256, 1)
gemm_mma(const __half* __restrict__ A, const __half* __restrict__ B,
         const float* __restrict__ bias, const float* __restrict__ R,
         float* __restrict__ C, __half* __restrict__ Ch,
         int M, int N, int K) {
    extern __shared__ __align__(1024) char smem[];
    const uint32_t sbase = smem_to_u32(smem);
    int tid = threadIdx.x;
    int wid = tid >> 5, lane = tid & 31;
    int bn = blockIdx.x * 128, bm = blockIdx.y * 128;

    const __half* Aptr = A + (size_t)bm*K;
    const int nch = K >> 6;

    auto issue = [&](int ch, int stg) {
        uint32_t sA = sbase + stg*32768;
        uint32_t sB = sA + 16384;
        const __half* srcA = Aptr + ch*64;
        #pragma unroll
        for (int rr = 0; rr < 4; rr++) {
            int idx = rr*256 + tid;
            int row = idx >> 3, u = idx & 7;
            const void* g = srcA + (size_t)row*K + u*8;
            uint32_t off = (uint32_t)(row*128 + u*16);
            CP_ASYNC16(sA + SWZA(off), g);
        }
        const __half* srcB = B + (size_t)(ch*64)*N + bn;
        #pragma unroll
        for (int rr = 0; rr < 4; rr++) {
            int idx = rr*256 + tid;
            int row = idx >> 4, u = idx & 15;
            const void* g = srcB + (size_t)row*N + u*8;
            uint32_t off = (uint32_t)(row*256 + u*16);
            CP_ASYNC16(sB + SWZB(off), g);
        }
    };

    int m0w = (wid >> 1) * 32, n0w = (wid & 1) * 64;
    int jj = lane >> 3, rr8 = lane & 7;
    int arow = m0w + (jj & 1)*8 + rr8;
    int acol = (jj >> 1) * 8;
    int btrow = lane & 15;
    int btcol = n0w + ((lane >> 4) << 3);

    float acc[2][8][4];
    #pragma unroll
    for (int mt = 0; mt < 2; mt++)
        #pragma unroll
        for (int nt = 0; nt < 8; nt++)
            #pragma unroll
            for (int r = 0; r < 4; r++) acc[mt][nt][r] = 0.f;

    issue(0, 0); CP_COMMIT();
    issue(1, 1); CP_COMMIT();
    issue(2, 2); CP_COMMIT();

    for (int ch = 0; ch < nch; ch++) {
        if (ch + 3 < nch) issue(ch + 3, (ch + 3) & (GSTAGES-1));
        CP_COMMIT();
        CP_WAIT3();
        __syncthreads();

        uint32_t sA = sbase + (ch & (GSTAGES-1))*32768;
        uint32_t sB = sA + 16384;
        #pragma unroll
        for (int kk = 0; kk < 4; kk++) {
            uint32_t a[2][4];
            #pragma unroll
            for (int mt = 0; mt < 2; mt++) {
                uint32_t off = (uint32_t)((arow + mt*16)*128 + (kk*16 + acol)*2);
                LDSM_X4(a[mt], sA + SWZA(off));
            }
            uint32_t bt[4][4];
            #pragma unroll
            for (int np = 0; np < 4; np++) {
                uint32_t off = (uint32_t)((kk*16 + btrow)*256 + (btcol + np*16)*2);
                LDSM_X4T(bt[np], sB + SWZB(off));
            }
            #pragma unroll
            for (int mt = 0; mt < 2; mt++)
                #pragma unroll
                for (int nt = 0; nt < 8; nt++)
                    MMA16816(acc[mt][nt], a[mt], bt[nt>>1][(nt&1)*2], bt[nt>>1][(nt&1)*2+1]);
        }
        __syncthreads();
    }

    int lr = lane >> 2, lc = (lane & 3) * 2;
    #pragma unroll
    for (int mt = 0; mt < 2; mt++) {
        #pragma unroll
        for (int nt = 0; nt < 8; nt++) {
            int col = bn + n0w + nt*8 + lc;
            float b0 = bias[col], b1 = bias[col+1];
            int r0 = bm + m0w + mt*16 + lr;
            #pragma unroll
            for (int half = 0; half < 2; half++) {
                int m = r0 + half*8;
                float v0 = acc[mt][nt][half*2]   + b0;
                float v1 = acc[mt][nt][half*2+1] + b1;
                if (GELU) { v0 = gelu_f(v0); v1 = gelu_f(v1); }
                size_t o = (size_t)m*N + col;
                if (HOUT) {
                    *(__half2*)(Ch + o) = __floats2half2_rn(v0, v1);
                } else {
                    if (RES) {
                        float2 rv = *(const float2*)(R + o);
                        v0 += rv.x; v1 += rv.y;
                    }
                    *(float2*)(C + o) = make_float2(v0, v1);
                }
            }
        }
    }
}

// ---------------- MMA flash attention ----------------
// CTA: (q-tile 32, one (n,h)). Two-pass: S = Q K^T (fp32, smem), softmax, O = P V.
// Q/K/V head-major fp16; Q pre-scaled by 1/8. K/V streamed in 64-row chunks, double-buffered.
#define QB 32
#define SSTR 584                 // fp32 stride (576+8), conflict-free
#define PSTR 584                 // fp16 stride
#define ATTN_SS   0
#define ATTN_SP   (QB*SSTR*4)                       // 74752
#define ATTN_SQ   (ATTN_SP + QB*PSTR*2)             // 112128
#define ATTN_SKV  (ATTN_SQ + QB*128)                // 116224
#define ATTN_SINV (ATTN_SKV + 2*8192)               // 132608
#define ATTN_SMEM (ATTN_SINV + 128)                 // 132736

__global__ void __launch_bounds__(256, 1)
attn_mma_k(const __half* __restrict__ Qh, const __half* __restrict__ Kh,
           const __half* __restrict__ Vh, __half* __restrict__ Oh) {
    extern __shared__ __align__(1024) char smem[];
    const uint32_t sb = smem_to_u32(smem);
    float* sS = (float*)(smem + ATTN_SS);
    float* sinvp = (float*)(smem + ATTN_SINV);
    int tid = threadIdx.x;
    int wid = tid >> 5, lane = tid & 31;
    int q0 = blockIdx.x * QB;
    int nh = blockIdx.y;                 // n*NHEAD + h
    int h  = nh % NHEAD, n = nh / NHEAD;

    const __half* qbase = Qh + ((size_t)nh*LTOK + q0)*HDIM;
    const __half* kbase = Kh + (size_t)nh*LTOK*HDIM;
    const __half* vbase = Vh + (size_t)nh*LTOK*HDIM;

    auto issue_kv = [&](const __half* base, int c, int buf) {
        uint32_t sdst = sb + ATTN_SKV + buf*8192;
        const __half* src = base + c*4096;
        #pragma unroll
        for (int it = 0; it < 2; it++) {
            int idx = it*256 + tid;
            CP_ASYNC16(sdst + SWZA((uint32_t)((idx>>3)*128 + (idx&7)*16)), src + idx*8);
        }
    };

    // prologue: Q + K0 in group 1, K1 in group 2
    {
        CP_ASYNC16(sb + ATTN_SQ + SWZA((uint32_t)((tid>>3)*128 + (tid&7)*16)), qbase + tid*8);
        issue_kv(kbase, 0, 0);
        CP_COMMIT();
        issue_kv(kbase, 1, 1);
        CP_COMMIT();
    }

    // ---- pass 1: S = Q K^T ----
    int wq = wid >> 2, wk = wid & 3;
    uint32_t afr[4][4];
    const int NCH = LTOK / 64;    // 9
    for (int c = 0; c < NCH; c++) {
        CP_WAIT1();
        __syncthreads();
        uint32_t sK = sb + ATTN_SKV + (c & 1)*8192;
        if (c == 0) {
            #pragma unroll
            for (int kk = 0; kk < 4; kk++) {
                uint32_t off = (uint32_t)((wq*16 + (lane & 15))*128 + (kk*16 + ((lane>>4)<<3))*2);
                LDSM_X4(afr[kk], sb + ATTN_SQ + SWZA(off));
            }
        }
        float acc[2][4];
        #pragma unroll
        for (int nt = 0; nt < 2; nt++)
            #pragma unroll
            for (int r = 0; r < 4; r++) acc[nt][r] = 0.f;
        #pragma unroll
        for (int kk = 0; kk < 4; kk++) {
            uint32_t bfr[4];
            uint32_t off = (uint32_t)((wk*16 + (lane & 15))*128 + (kk*16 + ((lane>>4)<<3))*2);
            LDSM_X4(bfr, sK + SWZA(off));
            MMA16816(acc[0], afr[kk], bfr[0], bfr[2]);
            MMA16816(acc[1], afr[kk], bfr[1], bfr[3]);
        }
        // store S
        int col0 = c*64 + wk*16 + (lane & 3)*2;
        int r = wq*16 + (lane >> 2);
        #pragma unroll
        for (int nt = 0; nt < 2; nt++) {
            *(float2*)&sS[r*SSTR + col0 + nt*8]       = make_float2(acc[nt][0], acc[nt][1]);
            *(float2*)&sS[(r+8)*SSTR + col0 + nt*8]   = make_float2(acc[nt][2], acc[nt][3]);
        }
        __syncthreads();
        if (c + 2 < NCH) issue_kv(kbase, c + 2, c & 1);
        CP_COMMIT();
    }

    // prefetch V0, V1 while softmax runs
    issue_kv(vbase, 0, 0); CP_COMMIT();
    issue_kv(vbase, 1, 1); CP_COMMIT();

    // ---- softmax: warp w handles rows 4w..4w+3 ----
    {
        __half* sP = (__half*)(smem + ATTN_SP);
        #pragma unroll
        for (int rr = 0; rr < 4; rr++) {
            int r = wid*4 + rr;
            float mx = -1e30f;
            for (int i = lane; i < LTOK; i += 32) mx = fmaxf(mx, sS[r*SSTR + i]);
            #pragma unroll
            for (int o = 16; o; o >>= 1) mx = fmaxf(mx, __shfl_xor_sync(0xffffffffu, mx, o));
            float sum = 0.f;
            for (int i = lane; i < LTOK; i += 32) {
                float e = __expf(sS[r*SSTR + i] - mx);
                sum += e;
                sP[r*PSTR + i] = __float2half_rn(e);
            }
            #pragma unroll
            for (int o = 16; o; o >>= 1) sum += __shfl_xor_sync(0xffffffffu, sum, o);
            if (lane == 0) sinvp[r] = 1.f / sum;
        }
    }
    __syncthreads();

    // ---- pass 2: O = P V ----
    int wn = wid & 3;
    float acc2[2][4];
    #pragma unroll
    for (int nt = 0; nt < 2; nt++)
        #pragma unroll
        for (int r = 0; r < 4; r++) acc2[nt][r] = 0.f;

    for (int c = 0; c < NCH; c++) {
        CP_WAIT1();
        __syncthreads();
        uint32_t sV = sb + ATTN_SKV + (c & 1)*8192;
        #pragma unroll
        for (int kk = 0; kk < 4; kk++) {
            uint32_t pa[4];
            uint32_t paddr = sb + ATTN_SP
                + (uint32_t)((wq*16 + (lane & 15))*(PSTR*2))
                + (uint32_t)((c*64 + kk*16 + ((lane>>4)<<3))*2);
            LDSM_X4(pa, paddr);
            uint32_t vb[4];
            uint32_t off = (uint32_t)((kk*16 + (lane & 15))*128 + (wn*16 + ((lane>>4)<<3))*2);
            LDSM_X4T(vb, sV + SWZA(off));
            MMA16816(acc2[0], pa, vb[0], vb[1]);
            MMA16816(acc2[1], pa, vb[2], vb[3]);
        }
        __syncthreads();
        if (c + 2 < NCH) issue_kv(vbase, c + 2, c & 1);
        CP_COMMIT();
    }

    // epilogue
    int r0 = wq*16 + (lane >> 2);
    #pragma unroll
    for (int half = 0; half < 2; half++) {
        int r = r0 + half*8;
        float is = sinvp[r];
        int gq = q0 + r;
        #pragma unroll
        for (int nt = 0; nt < 2; nt++) {
            int col = wn*16 + nt*8 + (lane & 3)*2;
            float v0 = acc2[nt][half*2]   * is;
            float v1 = acc2[nt][half*2+1] * is;
            *(__half2*)(Oh + ((size_t)(n*LTOK + gq))*WDIM + h*HDIM + col) =
                __floats2half2_rn(v0, v1);
        }
    }
}

// ---------------- final mean ----------------
__global__ void mean_k(const float* __restrict__ y, float* __restrict__ out) {
    int c = blockIdx.x*256 + threadIdx.x;
    int n = blockIdx.y;
    if (c >= WDIM) return;
    float acc = 0.f;
    for (int l = 0; l < LTOK; l++)
        acc += y[(size_t)(n*LTOK + l)*WDIM + c];
    out[(size_t)n*WDIM + c] = acc * (1.f/(float)LTOK);
}

// ---------------- host orchestration ----------------
extern "C" void kernel_launch(void* const* d_in, const int* in_sizes, int n_in,
                              void* d_out, int out_size) {
    const float* image     = (const float*)d_in[0];
    const float* conv_ker  = (const float*)d_in[1];
    const float* conv_bias = (const float*)d_in[2];
    const float* ln1_scale = (const float*)d_in[3];
    const float* ln1_bias  = (const float*)d_in[4];
    const float* wq        = (const float*)d_in[5];
    const float* bq        = (const float*)d_in[6];
    const float* wk        = (const float*)d_in[7];
    const float* bk        = (const float*)d_in[8];
    const float* wv        = (const float*)d_in[9];
    const float* bv        = (const float*)d_in[10];
    const float* wo        = (const float*)d_in[11];
    const float* bo        = (const float*)d_in[12];
    const float* ln2_scale = (const float*)d_in[13];
    const float* ln2_bias  = (const float*)d_in[14];
    const float* w1        = (const float*)d_in[15];
    const float* b1        = (const float*)d_in[16];
    const float* w2        = (const float*)d_in[17];
    const float* b2        = (const float*)d_in[18];
    const float* lnf_scale = (const float*)d_in[19];
    const float* lnf_bias  = (const float*)d_in[20];
    float* out = (float*)d_out;

    float *x, *y, *qkv, *rope, *bqkv;
    __half *yh, *oh, *qh, *kh, *vh, *h1h, *wh, *wqkvh;
    cudaGetSymbolAddress((void**)&x,    g_x);
    cudaGetSymbolAddress((void**)&y,    g_y);
    cudaGetSymbolAddress((void**)&qkv,  g_qkv);
    cudaGetSymbolAddress((void**)&rope, g_rope);
    cudaGetSymbolAddress((void**)&bqkv, g_bqkv);
    cudaGetSymbolAddress((void**)&yh,   g_yh);
    cudaGetSymbolAddress((void**)&oh,   g_oh);
    cudaGetSymbolAddress((void**)&qh,   g_qh);
    cudaGetSymbolAddress((void**)&kh,   g_kh);
    cudaGetSymbolAddress((void**)&vh,   g_vh);
    cudaGetSymbolAddress((void**)&h1h,  g_h1h);
    cudaGetSymbolAddress((void**)&wh,   g_wh);
    cudaGetSymbolAddress((void**)&wqkvh,g_wqkv);

    cudaFuncSetAttribute(gemm_mma<false,false,false>, cudaFuncAttributeMaxDynamicSharedMemorySize, GEMM_SMEM);
    cudaFuncSetAttribute(gemm_mma<false,true, false>, cudaFuncAttributeMaxDynamicSharedMemorySize, GEMM_SMEM);
    cudaFuncSetAttribute(gemm_mma<true, false,true >, cudaFuncAttributeMaxDynamicSharedMemorySize, GEMM_SMEM);
    cudaFuncSetAttribute(attn_mma_k, cudaFuncAttributeMaxDynamicSharedMemorySize, ATTN_SMEM);

    __half* w_conv = wh;
    __half* w_o    = wh + (size_t)1*C0;
    __half* w_1    = wh + (size_t)5*C0;
    __half* w_2    = wh + (size_t)21*C0;

    // weight prep
    wcvt_k<<<(unsigned)(((size_t)37*C0/4 + 255)/256), 256>>>(conv_ker, wo, w1, w2, wh);
    wqkvcvt_k<<<(unsigned)(((size_t)12*C0/4 + 255)/256), 256>>>(wq, wk, wv, wqkvh);
    bcat_k<<<(DEPTH*QKVN + 255)/256, 256>>>(bq, bk, bv, bqkv);
    rope_cache_k<<<(LTOK*16 + 255)/256, 256>>>(rope);

    // patch embed
    im2col_k<<<(NROWS*WDIM + 255)/256, 256>>>(image, h1h);
    {
        dim3 g(WDIM/128, NROWS/128);
        gemm_mma<false,false,false><<<g, 256, GEMM_SMEM>>>(h1h, w_conv, conv_bias,
                                                           nullptr, x, nullptr,
                                                           NROWS, WDIM, WDIM);
    }

    dim3 gProj(WDIM/128, NROWS/128);     // 6 x 36
    dim3 gQkv (QKVN/128, NROWS/128);     // 18 x 36
    dim3 gMlp1(MLPDIM/128, NROWS/128);   // 24 x 36
    const int cvtTot = BATCH*LTOK*NHEAD*32;
    dim3 gCvt((cvtTot + 255)/256, 3);
    dim3 gAttn(LTOK/QB, BATCH*NHEAD);    // 18 x 96

    for (int l = 0; l < DEPTH; l++) {
        const __half* wqkv_l = wqkvh + (size_t)l*3*C0;
        const __half* wo_l   = w_o + (size_t)l*C0;
        const __half* w1_l   = w_1 + (size_t)l*4*C0;
        const __half* w2_l   = w_2 + (size_t)l*4*C0;
        const float* bqkv_l = bqkv + (size_t)l*QKVN;
        const float* bo_l = bo + (size_t)l*WDIM;
        const float* b1_l = b1 + (size_t)l*MLPDIM;
        const float* b2_l = b2 + (size_t)l*WDIM;

        ln_k<<<NROWS, 256>>>(x, nullptr, yh, ln1_scale + (size_t)l*WDIM, ln1_bias + (size_t)l*WDIM);

        gemm_mma<false,false,false><<<gQkv, 256, GEMM_SMEM>>>(yh, wqkv_l, bqkv_l, nullptr, qkv, nullptr, NROWS, QKVN, WDIM);

        qkvcvt_k<<<gCvt, 256>>>(qkv, rope, qh, kh, vh);

        attn_mma_k<<<gAttn, 256, ATTN_SMEM>>>(qh, kh, vh, oh);

        gemm_mma<false,true,false><<<gProj, 256, GEMM_SMEM>>>(oh, wo_l, bo_l, x, x, nullptr, NROWS, WDIM, WDIM);

        ln_k<<<NROWS, 256>>>(x, nullptr, yh, ln2_scale + (size_t)l*WDIM, ln2_bias + (size_t)l*WDIM);

        gemm_mma<true,false,true><<<gMlp1, 256, GEMM_SMEM>>>(yh, w1_l, b1_l, nullptr, nullptr, h1h, NROWS, MLPDIM, WDIM);
        gemm_mma<false,true,false><<<gProj, 256, GEMM_SMEM>>>(h1h, w2_l, b2_l, x, x, nullptr, NROWS, WDIM, MLPDIM);
    }

    ln_k<<<NROWS, 256>>>(x, y, yh, lnf_scale, lnf_bias);
    {
        dim3 g((WDIM + 255)/256, BATCH);
        mean_k<<<g, 256>>>(y, out);
    }
}

// round 7
// speedup vs baseline: 13.8158x; 1.2437x over previous
#include <cuda_runtime.h>
#include <cuda_fp16.h>
#include <cstdint>
#include <cstddef>

// ---------------- problem constants ----------------
#define BATCH   8
#define IMG     384
#define CIN     3
#define PATCH   16
#define GRIDP   24
#define LTOK    576
#define WDIM    768
#define DEPTH   4
#define NHEAD   12
#define HDIM    64
#define MLPDIM  3072
#define NROWS   (BATCH*LTOK)
#define EPS     1e-6f
#define QKVN    (3*WDIM)            // 2304

// ---------------- PTX helpers ----------------
__device__ __forceinline__ uint32_t smem_to_u32(const void* smem_ptr) {
    uint32_t addr;
    asm("{ .reg .u64 tmp; cvta.to.shared.u64 tmp, %1; cvt.u32.u64 %0, tmp; }"
        : "=r"(addr) : "l"(smem_ptr));
    return addr;
}
#define CP_ASYNC16(dst, src) \
    asm volatile("cp.async.cg.shared.global [%0], [%1], 16;" :: "r"(dst), "l"(src) : "memory")
#define CP_COMMIT() asm volatile("cp.async.commit_group;" ::: "memory")
#define CP_WAIT2()  asm volatile("cp.async.wait_group 2;" ::: "memory")
#define CP_WAIT1()  asm volatile("cp.async.wait_group 1;" ::: "memory")

#define LDSM_X4(r, addr) \
    asm volatile("ldmatrix.sync.aligned.m8n8.x4.shared.b16 {%0,%1,%2,%3}, [%4];" \
        : "=r"((r)[0]), "=r"((r)[1]), "=r"((r)[2]), "=r"((r)[3]) : "r"(addr))
#define LDSM_X4T(r, addr) \
    asm volatile("ldmatrix.sync.aligned.m8n8.x4.trans.shared.b16 {%0,%1,%2,%3}, [%4];" \
        : "=r"((r)[0]), "=r"((r)[1]), "=r"((r)[2]), "=r"((r)[3]) : "r"(addr))

#define MMA16816(d, a, b0, b1) \
    asm volatile("mma.sync.aligned.m16n8k16.row.col.f32.f16.f16.f32 " \
        "{%0,%1,%2,%3}, {%4,%5,%6,%7}, {%8,%9}, {%0,%1,%2,%3};" \
        : "+f"((d)[0]), "+f"((d)[1]), "+f"((d)[2]), "+f"((d)[3]) \
        : "r"((a)[0]), "r"((a)[1]), "r"((a)[2]), "r"((a)[3]), "r"(b0), "r"(b1))

#define SWZA(off) ((off) ^ (((off) >> 3) & 0x70))   // 128B rows
#define SWZB(off) ((off) ^ (((off) >> 4) & 0x70))   // 256B rows

// ---------------- scratch ----------------
__device__ __align__(256) float g_x   [NROWS*WDIM];
__device__ __align__(256) float g_y   [NROWS*WDIM];
__device__ __align__(256) float g_qkv [NROWS*QKVN];
__device__ __align__(256) float g_rope[4*LTOK*16];
__device__ __align__(256) float g_bqkv[DEPTH*QKVN];

__device__ __align__(256) __half g_yh [NROWS*WDIM];
__device__ __align__(256) __half g_oh [NROWS*WDIM];
__device__ __align__(256) __half g_qh [NROWS*WDIM];
__device__ __align__(256) __half g_kh [NROWS*WDIM];
__device__ __align__(256) __half g_vh [NROWS*WDIM];
__device__ __align__(256) __half g_h1h[NROWS*MLPDIM];

#define C0 589824
__device__ __align__(256) __half g_wh  [37*C0];      // [conv][wo x4][w1 x4][w2 x4]
__device__ __align__(256) __half g_wqkv[12*C0];      // [l][768][2304]

// ---------------- small helpers ----------------
__device__ __forceinline__ float gelu_f(float x) {
    float u = 0.7978845608028654f*(x + 0.044715f*x*x*x);
    float t = __expf(2.f*u);
    float th = 1.f - __fdividef(2.f, t + 1.f);     // tanh(u), inf-safe
    return 0.5f*x*(1.f + th);
}

// ---------------- weight convert (conv, wo, w1, w2) ----------------
__global__ void wcvt_k(const float* __restrict__ conv, const float* __restrict__ wo,
                       const float* __restrict__ w1, const float* __restrict__ w2,
                       __half* __restrict__ dst) {
    size_t i4 = ((size_t)blockIdx.x*256 + threadIdx.x) * 4;
    if (i4 >= (size_t)37*C0) return;
    const float* src; size_t off;
    if      (i4 < (size_t)C0)    { src = conv; off = i4; }
    else if (i4 < (size_t)5*C0)  { src = wo;   off = i4 - (size_t)C0; }
    else if (i4 < (size_t)21*C0) { src = w1;   off = i4 - (size_t)5*C0; }
    else                         { src = w2;   off = i4 - (size_t)21*C0; }
    float4 v = *(const float4*)(src + off);
    __half2* d = (__half2*)(dst + i4);
    d[0] = __floats2half2_rn(v.x, v.y);
    d[1] = __floats2half2_rn(v.z, v.w);
}

// ---------------- qkv weight interleave: [l][k][2304] ----------------
__global__ void wqkvcvt_k(const float* __restrict__ wq, const float* __restrict__ wk,
                          const float* __restrict__ wv, __half* __restrict__ dst) {
    size_t i4 = ((size_t)blockIdx.x*256 + threadIdx.x) * 4;
    if (i4 >= (size_t)12*C0) return;
    size_t l  = i4 / ((size_t)WDIM*QKVN);
    size_t r  = i4 % ((size_t)WDIM*QKVN);
    size_t k  = r / QKVN;
    size_t j  = r % QKVN;
    size_t blk = j / WDIM;
    const float* src = (blk == 0) ? wq : (blk == 1) ? wk : wv;
    float4 v = *(const float4*)(src + l*(size_t)C0 + k*WDIM + (j - blk*WDIM));
    __half2* d = (__half2*)(dst + i4);
    d[0] = __floats2half2_rn(v.x, v.y);
    d[1] = __floats2half2_rn(v.z, v.w);
}

__global__ void bcat_k(const float* __restrict__ bq, const float* __restrict__ bk,
                       const float* __restrict__ bv, float* __restrict__ dst) {
    int idx = blockIdx.x*256 + threadIdx.x;
    if (idx >= DEPTH*QKVN) return;
    int l = idx / QKVN, j = idx % QKVN;
    int blk = j / WDIM;
    const float* src = (blk == 0) ? bq : (blk == 1) ? bk : bv;
    dst[idx] = src[l*WDIM + (j - blk*WDIM)];
}

// ---------------- im2col (fp16) ----------------
__global__ void im2col_k(const float* __restrict__ img, __half* __restrict__ oh) {
    int idx = blockIdx.x*256 + threadIdx.x;
    if (idx >= NROWS*WDIM) return;
    int t  = idx % WDIM;
    int nl = idx / WDIM;
    int l  = nl % LTOK;
    int n  = nl / LTOK;
    int ci = t % 3;
    int ij = t / 3;
    int j  = ij % PATCH;
    int i  = ij / PATCH;
    int px = l % GRIDP, py = l / GRIDP;
    float v = img[ (((size_t)n*IMG + (py*PATCH+i))*IMG + (px*PATCH+j))*CIN + ci ];
    oh[idx] = __float2half_rn(v);
}

// ---------------- rope cache ----------------
__global__ void rope_cache_k(float* __restrict__ cache) {
    int idx = blockIdx.x*256 + threadIdx.x;
    if (idx >= LTOK*16) return;
    int f = idx % 16, l = idx / 16;
    float freq = (float)f / (15.f + 1e-9f);
    float inv  = powf(10000.f, -freq);
    float u = ((float)(l % GRIDP) + 0.5f) / (float)GRIDP;
    float v = ((float)(l / GRIDP) + 0.5f) / (float)GRIDP;
    float ax = u*inv, ay = v*inv;
    cache[0*LTOK*16 + idx] = cosf(ax);
    cache[1*LTOK*16 + idx] = sinf(ax);
    cache[2*LTOK*16 + idx] = cosf(ay);
    cache[3*LTOK*16 + idx] = sinf(ay);
}

// ---------------- qkv -> head-major fp16 (rope on q,k; q scaled by 1/8) ----------------
__global__ void qkvcvt_k(const float* __restrict__ qkv, const float* __restrict__ cache,
                         __half* __restrict__ qh, __half* __restrict__ kh,
                         __half* __restrict__ vh) {
    int idx = blockIdx.x*256 + threadIdx.x;
    const int TOT = BATCH*LTOK*NHEAD*32;
    if (idx >= TOT) return;
    int p  = idx & 31;
    int h  = (idx >> 5) % NHEAD;
    int l  = (idx >> 5) / NHEAD % LTOK;
    int n  = (idx >> 5) / (NHEAD*LTOK);
    size_t srow = (size_t)(n*LTOK + l)*QKVN;
    size_t dsto = ((size_t)(n*NHEAD + h)*LTOK + l)*HDIM + 2*p;
    int plane = blockIdx.y;
    if (plane == 2) {
        float v0 = qkv[srow + 2*WDIM + h*HDIM + 2*p];
        float v1 = qkv[srow + 2*WDIM + h*HDIM + 2*p + 1];
        *(__half2*)(vh + dsto) = __floats2half2_rn(v0, v1);
    } else {
        float c, s;
        if (p < 16) { c = cache[0*LTOK*16 + l*16 + p];    s = cache[1*LTOK*16 + l*16 + p]; }
        else        { c = cache[2*LTOK*16 + l*16 + p-16]; s = cache[3*LTOK*16 + l*16 + p-16]; }
        size_t so = srow + (plane ? WDIM : 0) + h*HDIM + 2*p;
        float x = qkv[so], y = qkv[so + 1];
        float rx = x*c - y*s, ry = x*s + y*c;
        if (plane == 0) { rx *= 0.125f; ry *= 0.125f; *(__half2*)(qh + dsto) = __floats2half2_rn(rx, ry); }
        else            { *(__half2*)(kh + dsto) = __floats2half2_rn(rx, ry); }
    }
}

// ---------------- layernorm: warp per row (8 rows / 256-thread block) ----------------
__global__ void ln_k(const float* __restrict__ x, float* __restrict__ y,
                     __half* __restrict__ yh,
                     const float* __restrict__ sc, const float* __restrict__ bi) {
    int wid = threadIdx.x >> 5, lane = threadIdx.x & 31;
    int row = blockIdx.x*8 + wid;
    const float4* xr = (const float4*)(x + (size_t)row*WDIM);
    float4 v[6];
    float s = 0.f, sq = 0.f;
    #pragma unroll
    for (int j = 0; j < 6; j++) {
        v[j] = xr[lane + j*32];
        s  += v[j].x + v[j].y + v[j].z + v[j].w;
        sq += v[j].x*v[j].x + v[j].y*v[j].y + v[j].z*v[j].z + v[j].w*v[j].w;
    }
    #pragma unroll
    for (int o = 16; o; o >>= 1) {
        s  += __shfl_xor_sync(0xffffffffu, s,  o);
        sq += __shfl_xor_sync(0xffffffffu, sq, o);
    }
    float m   = s * (1.f/(float)WDIM);
    float var = sq * (1.f/(float)WDIM) - m*m;
    float inv = rsqrtf(var + EPS);
    size_t base = (size_t)row*WDIM;
    #pragma unroll
    for (int j = 0; j < 6; j++) {
        int c = (lane + j*32)*4;
        float4 scv = *(const float4*)(sc + c);
        float4 biv = *(const float4*)(bi + c);
        float o0 = (v[j].x - m)*inv*scv.x + biv.x;
        float o1 = (v[j].y - m)*inv*scv.y + biv.y;
        float o2 = (v[j].z - m)*inv*scv.z + biv.z;
        float o3 = (v[j].w - m)*inv*scv.w + biv.w;
        if (y) *(float4*)(y + base + c) = make_float4(o0, o1, o2, o3);
        __half2 h0 = __floats2half2_rn(o0, o1);
        __half2 h1 = __floats2half2_rn(o2, o3);
        *(uint2*)(yh + base + c) = make_uint2(*(uint32_t*)&h0, *(uint32_t*)&h1);
    }
}

// ---------------- fp16 tensor-core GEMM: 128 threads, tile 64x128, 3 stages ----------------
// 3 CTAs/SM target: 72KB smem/CTA, reg cap 170.
#define GSTAGES 3
#define STAGE_BYTES 24576            // A 64x64 (8KB, SWZA) + B 64x128 (16KB, SWZB)
#define GEMM_SMEM (GSTAGES*STAGE_BYTES)

template<bool GELU, bool RES, bool HOUT>
__global__ void __launch_bounds__(128, 3)
gemm_mma(const __half* __restrict__ A, const __half* __restrict__ B,
         const float* __restrict__ bias, const float* __restrict__ R,
         float* __restrict__ C, __half* __restrict__ Ch,
         int M, int N, int K) {
    extern __shared__ __align__(1024) char smem[];
    const uint32_t sbase = smem_to_u32(smem);
    int tid = threadIdx.x;
    int wid = tid >> 5, lane = tid & 31;
    int bn = blockIdx.x * 128, bm = blockIdx.y * 64;

    const __half* Aptr = A + (size_t)bm*K;
    const int nch = K >> 6;

    auto issue = [&](int ch, int stg) {
        uint32_t sA = sbase + stg*STAGE_BYTES;
        uint32_t sB = sA + 8192;
        const __half* srcA = Aptr + ch*64;
        #pragma unroll
        for (int rr = 0; rr < 4; rr++) {
            int idx = rr*128 + tid;
            int row = idx >> 3, u = idx & 7;
            CP_ASYNC16(sA + SWZA((uint32_t)(row*128 + u*16)), srcA + (size_t)row*K + u*8);
        }
        const __half* srcB = B + (size_t)(ch*64)*N + bn;
        #pragma unroll
        for (int rr = 0; rr < 8; rr++) {
            int idx = rr*128 + tid;
            int row = idx >> 4, u = idx & 15;
            CP_ASYNC16(sB + SWZB((uint32_t)(row*256 + u*16)), srcB + (size_t)row*N + u*8);
        }
    };

    // 2 warps (M) x 2 warps (N); warp tile 32x64
    int m0w = (wid >> 1) * 32, n0w = (wid & 1) * 64;
    int jj = lane >> 3, rr8 = lane & 7;
    int arow = m0w + (jj & 1)*8 + rr8;
    int acol = (jj >> 1) * 8;
    int btrow = lane & 15;
    int btcol = n0w + ((lane >> 4) << 3);

    float acc[2][8][4];
    #pragma unroll
    for (int mt = 0; mt < 2; mt++)
        #pragma unroll
        for (int nt = 0; nt < 8; nt++)
            #pragma unroll
            for (int r = 0; r < 4; r++) acc[mt][nt][r] = 0.f;

    issue(0, 0); CP_COMMIT();
    issue(1, 1); CP_COMMIT();

    for (int ch = 0; ch < nch; ch++) {
        if (ch + 2 < nch) issue(ch + 2, (ch + 2) % GSTAGES);
        CP_COMMIT();
        CP_WAIT2();
        __syncthreads();

        uint32_t sA = sbase + (ch % GSTAGES)*STAGE_BYTES;
        uint32_t sB = sA + 8192;
        #pragma unroll
        for (int kk = 0; kk < 4; kk++) {
            uint32_t a[2][4];
            #pragma unroll
            for (int mt = 0; mt < 2; mt++) {
                uint32_t off = (uint32_t)((arow + mt*16)*128 + (kk*16 + acol)*2);
                LDSM_X4(a[mt], sA + SWZA(off));
            }
            uint32_t bt[4][4];
            #pragma unroll
            for (int np = 0; np < 4; np++) {
                uint32_t off = (uint32_t)((kk*16 + btrow)*256 + (btcol + np*16)*2);
                LDSM_X4T(bt[np], sB + SWZB(off));
            }
            #pragma unroll
            for (int mt = 0; mt < 2; mt++)
                #pragma unroll
                for (int nt = 0; nt < 8; nt++)
                    MMA16816(acc[mt][nt], a[mt], bt[nt>>1][(nt&1)*2], bt[nt>>1][(nt&1)*2+1]);
        }
        __syncthreads();
    }

    int lr = lane >> 2, lc = (lane & 3) * 2;
    #pragma unroll
    for (int mt = 0; mt < 2; mt++) {
        #pragma unroll
        for (int nt = 0; nt < 8; nt++) {
            int col = bn + n0w + nt*8 + lc;
            float b0 = bias[col], b1 = bias[col+1];
            int r0 = bm + m0w + mt*16 + lr;
            #pragma unroll
            for (int half = 0; half < 2; half++) {
                int m = r0 + half*8;
                float v0 = acc[mt][nt][half*2]   + b0;
                float v1 = acc[mt][nt][half*2+1] + b1;
                if (GELU) { v0 = gelu_f(v0); v1 = gelu_f(v1); }
                size_t o = (size_t)m*N + col;
                if (HOUT) {
                    *(__half2*)(Ch + o) = __floats2half2_rn(v0, v1);
                } else {
                    if (RES) {
                        float2 rv = *(const float2*)(R + o);
                        v0 += rv.x; v1 += rv.y;
                    }
                    *(float2*)(C + o) = make_float2(v0, v1);
                }
            }
        }
    }
}

// ---------------- MMA flash attention (unchanged from R6) ----------------
#define QB 32
#define SSTR 584
#define PSTR 584
#define ATTN_SS   0
#define ATTN_SP   (QB*SSTR*4)
#define ATTN_SQ   (ATTN_SP + QB*PSTR*2)
#define ATTN_SKV  (ATTN_SQ + QB*128)
#define ATTN_SINV (ATTN_SKV + 2*8192)
#define ATTN_SMEM (ATTN_SINV + 128)

__global__ void __launch_bounds__(256, 1)
attn_mma_k(const __half* __restrict__ Qh, const __half* __restrict__ Kh,
           const __half* __restrict__ Vh, __half* __restrict__ Oh) {
    extern __shared__ __align__(1024) char smem[];
    const uint32_t sb = smem_to_u32(smem);
    float* sS = (float*)(smem + ATTN_SS);
    float* sinvp = (float*)(smem + ATTN_SINV);
    int tid = threadIdx.x;
    int wid = tid >> 5, lane = tid & 31;
    int q0 = blockIdx.x * QB;
    int nh = blockIdx.y;
    int h  = nh % NHEAD, n = nh / NHEAD;

    const __half* qbase = Qh + ((size_t)nh*LTOK + q0)*HDIM;
    const __half* kbase = Kh + (size_t)nh*LTOK*HDIM;
    const __half* vbase = Vh + (size_t)nh*LTOK*HDIM;

    auto issue_kv = [&](const __half* base, int c, int buf) {
        uint32_t sdst = sb + ATTN_SKV + buf*8192;
        const __half* src = base + c*4096;
        #pragma unroll
        for (int it = 0; it < 2; it++) {
            int idx = it*256 + tid;
            CP_ASYNC16(sdst + SWZA((uint32_t)((idx>>3)*128 + (idx&7)*16)), src + idx*8);
        }
    };

    {
        CP_ASYNC16(sb + ATTN_SQ + SWZA((uint32_t)((tid>>3)*128 + (tid&7)*16)), qbase + tid*8);
        issue_kv(kbase, 0, 0);
        CP_COMMIT();
        issue_kv(kbase, 1, 1);
        CP_COMMIT();
    }

    int wq = wid >> 2, wk = wid & 3;
    uint32_t afr[4][4];
    const int NCH = LTOK / 64;
    for (int c = 0; c < NCH; c++) {
        CP_WAIT1();
        __syncthreads();
        uint32_t sK = sb + ATTN_SKV + (c & 1)*8192;
        if (c == 0) {
            #pragma unroll
            for (int kk = 0; kk < 4; kk++) {
                uint32_t off = (uint32_t)((wq*16 + (lane & 15))*128 + (kk*16 + ((lane>>4)<<3))*2);
                LDSM_X4(afr[kk], sb + ATTN_SQ + SWZA(off));
            }
        }
        float acc[2][4];
        #pragma unroll
        for (int nt = 0; nt < 2; nt++)
            #pragma unroll
            for (int r = 0; r < 4; r++) acc[nt][r] = 0.f;
        #pragma unroll
        for (int kk = 0; kk < 4; kk++) {
            uint32_t bfr[4];
            uint32_t off = (uint32_t)((wk*16 + (lane & 15))*128 + (kk*16 + ((lane>>4)<<3))*2);
            LDSM_X4(bfr, sK + SWZA(off));
            MMA16816(acc[0], afr[kk], bfr[0], bfr[2]);
            MMA16816(acc[1], afr[kk], bfr[1], bfr[3]);
        }
        int col0 = c*64 + wk*16 + (lane & 3)*2;
        int r = wq*16 + (lane >> 2);
        #pragma unroll
        for (int nt = 0; nt < 2; nt++) {
            *(float2*)&sS[r*SSTR + col0 + nt*8]       = make_float2(acc[nt][0], acc[nt][1]);
            *(float2*)&sS[(r+8)*SSTR + col0 + nt*8]   = make_float2(acc[nt][2], acc[nt][3]);
        }
        __syncthreads();
        if (c + 2 < NCH) issue_kv(kbase, c + 2, c & 1);
        CP_COMMIT();
    }

    issue_kv(vbase, 0, 0); CP_COMMIT();
    issue_kv(vbase, 1, 1); CP_COMMIT();

    {
        __half* sP = (__half*)(smem + ATTN_SP);
        #pragma unroll
        for (int rr = 0; rr < 4; rr++) {
            int r = wid*4 + rr;
            float mx = -1e30f;
            for (int i = lane; i < LTOK; i += 32) mx = fmaxf(mx, sS[r*SSTR + i]);
            #pragma unroll
            for (int o = 16; o; o >>= 1) mx = fmaxf(mx, __shfl_xor_sync(0xffffffffu, mx, o));
            float sum = 0.f;
            for (int i = lane; i < LTOK; i += 32) {
                float e = __expf(sS[r*SSTR + i] - mx);
                sum += e;
                sP[r*PSTR + i] = __float2half_rn(e);
            }
            #pragma unroll
            for (int o = 16; o; o >>= 1) sum += __shfl_xor_sync(0xffffffffu, sum, o);
            if (lane == 0) sinvp[r] = 1.f / sum;
        }
    }
    __syncthreads();

    int wn = wid & 3;
    float acc2[2][4];
    #pragma unroll
    for (int nt = 0; nt < 2; nt++)
        #pragma unroll
        for (int r = 0; r < 4; r++) acc2[nt][r] = 0.f;

    for (int c = 0; c < NCH; c++) {
        CP_WAIT1();
        __syncthreads();
        uint32_t sV = sb + ATTN_SKV + (c & 1)*8192;
        #pragma unroll
        for (int kk = 0; kk < 4; kk++) {
            uint32_t pa[4];
            uint32_t paddr = sb + ATTN_SP
                + (uint32_t)((wq*16 + (lane & 15))*(PSTR*2))
                + (uint32_t)((c*64 + kk*16 + ((lane>>4)<<3))*2);
            LDSM_X4(pa, paddr);
            uint32_t vb[4];
            uint32_t off = (uint32_t)((kk*16 + (lane & 15))*128 + (wn*16 + ((lane>>4)<<3))*2);
            LDSM_X4T(vb, sV + SWZA(off));
            MMA16816(acc2[0], pa, vb[0], vb[1]);
            MMA16816(acc2[1], pa, vb[2], vb[3]);
        }
        __syncthreads();
        if (c + 2 < NCH) issue_kv(vbase, c + 2, c & 1);
        CP_COMMIT();
    }

    int r0 = wq*16 + (lane >> 2);
    #pragma unroll
    for (int half = 0; half < 2; half++) {
        int r = r0 + half*8;
        float is = sinvp[r];
        int gq = q0 + r;
        #pragma unroll
        for (int nt = 0; nt < 2; nt++) {
            int col = wn*16 + nt*8 + (lane & 3)*2;
            float v0 = acc2[nt][half*2]   * is;
            float v1 = acc2[nt][half*2+1] * is;
            *(__half2*)(Oh + ((size_t)(n*LTOK + gq))*WDIM + h*HDIM + col) =
                __floats2half2_rn(v0, v1);
        }
    }
}

// ---------------- final mean ----------------
__global__ void mean_k(const float* __restrict__ y, float* __restrict__ out) {
    int c = blockIdx.x*256 + threadIdx.x;
    int n = blockIdx.y;
    if (c >= WDIM) return;
    float acc = 0.f;
    for (int l = 0; l < LTOK; l++)
        acc += y[(size_t)(n*LTOK + l)*WDIM + c];
    out[(size_t)n*WDIM + c] = acc * (1.f/(float)LTOK);
}

// ---------------- host orchestration ----------------
extern "C" void kernel_launch(void* const* d_in, const int* in_sizes, int n_in,
                              void* d_out, int out_size) {
    const float* image     = (const float*)d_in[0];
    const float* conv_ker  = (const float*)d_in[1];
    const float* conv_bias = (const float*)d_in[2];
    const float* ln1_scale = (const float*)d_in[3];
    const float* ln1_bias  = (const float*)d_in[4];
    const float* wq        = (const float*)d_in[5];
    const float* bq        = (const float*)d_in[6];
    const float* wk        = (const float*)d_in[7];
    const float* bk        = (const float*)d_in[8];
    const float* wv        = (const float*)d_in[9];
    const float* bv        = (const float*)d_in[10];
    const float* wo        = (const float*)d_in[11];
    const float* bo        = (const float*)d_in[12];
    const float* ln2_scale = (const float*)d_in[13];
    const float* ln2_bias  = (const float*)d_in[14];
    const float* w1        = (const float*)d_in[15];
    const float* b1        = (const float*)d_in[16];
    const float* w2        = (const float*)d_in[17];
    const float* b2        = (const float*)d_in[18];
    const float* lnf_scale = (const float*)d_in[19];
    const float* lnf_bias  = (const float*)d_in[20];
    float* out = (float*)d_out;

    float *x, *y, *qkv, *rope, *bqkv;
    __half *yh, *oh, *qh, *kh, *vh, *h1h, *wh, *wqkvh;
    cudaGetSymbolAddress((void**)&x,    g_x);
    cudaGetSymbolAddress((void**)&y,    g_y);
    cudaGetSymbolAddress((void**)&qkv,  g_qkv);
    cudaGetSymbolAddress((void**)&rope, g_rope);
    cudaGetSymbolAddress((void**)&bqkv, g_bqkv);
    cudaGetSymbolAddress((void**)&yh,   g_yh);
    cudaGetSymbolAddress((void**)&oh,   g_oh);
    cudaGetSymbolAddress((void**)&qh,   g_qh);
    cudaGetSymbolAddress((void**)&kh,   g_kh);
    cudaGetSymbolAddress((void**)&vh,   g_vh);
    cudaGetSymbolAddress((void**)&h1h,  g_h1h);
    cudaGetSymbolAddress((void**)&wh,   g_wh);
    cudaGetSymbolAddress((void**)&wqkvh,g_wqkv);

    cudaFuncSetAttribute(gemm_mma<false,false,false>, cudaFuncAttributeMaxDynamicSharedMemorySize, GEMM_SMEM);
    cudaFuncSetAttribute(gemm_mma<false,true, false>, cudaFuncAttributeMaxDynamicSharedMemorySize, GEMM_SMEM);
    cudaFuncSetAttribute(gemm_mma<true, false,true >, cudaFuncAttributeMaxDynamicSharedMemorySize, GEMM_SMEM);
    cudaFuncSetAttribute(attn_mma_k, cudaFuncAttributeMaxDynamicSharedMemorySize, ATTN_SMEM);

    __half* w_conv = wh;
    __half* w_o    = wh + (size_t)1*C0;
    __half* w_1    = wh + (size_t)5*C0;
    __half* w_2    = wh + (size_t)21*C0;

    wcvt_k<<<(unsigned)(((size_t)37*C0/4 + 255)/256), 256>>>(conv_ker, wo, w1, w2, wh);
    wqkvcvt_k<<<(unsigned)(((size_t)12*C0/4 + 255)/256), 256>>>(wq, wk, wv, wqkvh);
    bcat_k<<<(DEPTH*QKVN + 255)/256, 256>>>(bq, bk, bv, bqkv);
    rope_cache_k<<<(LTOK*16 + 255)/256, 256>>>(rope);

    im2col_k<<<(NROWS*WDIM + 255)/256, 256>>>(image, h1h);
    {
        dim3 g(WDIM/128, NROWS/64);
        gemm_mma<false,false,false><<<g, 128, GEMM_SMEM>>>(h1h, w_conv, conv_bias,
                                                           nullptr, x, nullptr,
                                                           NROWS, WDIM, WDIM);
    }

    dim3 gProj(WDIM/128,  NROWS/64);   // 6 x 72
    dim3 gQkv (QKVN/128,  NROWS/64);   // 18 x 72
    dim3 gMlp1(MLPDIM/128,NROWS/64);   // 24 x 72
    const int cvtTot = BATCH*LTOK*NHEAD*32;
    dim3 gCvt((cvtTot + 255)/256, 3);
    dim3 gAttn(LTOK/QB, BATCH*NHEAD);

    for (int l = 0; l < DEPTH; l++) {
        const __half* wqkv_l = wqkvh + (size_t)l*3*C0;
        const __half* wo_l   = w_o + (size_t)l*C0;
        const __half* w1_l   = w_1 + (size_t)l*4*C0;
        const __half* w2_l   = w_2 + (size_t)l*4*C0;
        const float* bqkv_l = bqkv + (size_t)l*QKVN;
        const float* bo_l = bo + (size_t)l*WDIM;
        const float* b1_l = b1 + (size_t)l*MLPDIM;
        const float* b2_l = b2 + (size_t)l*WDIM;

        ln_k<<<NROWS/8, 256>>>(x, nullptr, yh, ln1_scale + (size_t)l*WDIM, ln1_bias + (size_t)l*WDIM);

        gemm_mma<false,false,false><<<gQkv, 128, GEMM_SMEM>>>(yh, wqkv_l, bqkv_l, nullptr, qkv, nullptr, NROWS, QKVN, WDIM);

        qkvcvt_k<<<gCvt, 256>>>(qkv, rope, qh, kh, vh);

        attn_mma_k<<<gAttn, 256, ATTN_SMEM>>>(qh, kh, vh, oh);

        gemm_mma<false,true,false><<<gProj, 128, GEMM_SMEM>>>(oh, wo_l, bo_l, x, x, nullptr, NROWS, WDIM, WDIM);

        ln_k<<<NROWS/8, 256>>>(x, nullptr, yh, ln2_scale + (size_t)l*WDIM, ln2_bias + (size_t)l*WDIM);

        gemm_mma<true,false,true><<<gMlp1, 128, GEMM_SMEM>>>(yh, w1_l, b1_l, nullptr, nullptr, h1h, NROWS, MLPDIM, WDIM);
        gemm_mma<false,true,false><<<gProj, 128, GEMM_SMEM>>>(h1h, w2_l, b2_l, x, x, nullptr, NROWS, WDIM, MLPDIM);
    }

    ln_k<<<NROWS/8, 256>>>(x, y, yh, lnf_scale, lnf_bias);
    {
        dim3 g((WDIM + 255)/256, BATCH);
        mean_k<<<g, 256>>>(y, out);
    }
}

// round 9
// speedup vs baseline: 18.2889x; 1.3238x over previous
#include <cuda_runtime.h>
#include <cuda_fp16.h>
#include <cstdint>
#include <cstddef>

// ---------------- problem constants ----------------
#define BATCH   8
#define IMG     384
#define CIN     3
#define PATCH   16
#define GRIDP   24
#define LTOK    576
#define WDIM    768
#define DEPTH   4
#define NHEAD   12
#define HDIM    64
#define MLPDIM  3072
#define NROWS   (BATCH*LTOK)
#define EPS     1e-6f
#define QKVN    (3*WDIM)            // 2304

// ---------------- PTX helpers ----------------
__device__ __forceinline__ uint32_t smem_to_u32(const void* smem_ptr) {
    uint32_t addr;
    asm("{ .reg .u64 tmp; cvta.to.shared.u64 tmp, %1; cvt.u32.u64 %0, tmp; }"
        : "=r"(addr) : "l"(smem_ptr));
    return addr;
}
#define CP_ASYNC16(dst, src) \
    asm volatile("cp.async.cg.shared.global [%0], [%1], 16;" :: "r"(dst), "l"(src) : "memory")
#define CP_COMMIT() asm volatile("cp.async.commit_group;" ::: "memory")
#define CP_WAIT2()  asm volatile("cp.async.wait_group 2;" ::: "memory")
#define CP_WAIT1()  asm volatile("cp.async.wait_group 1;" ::: "memory")

#define LDSM_X4(r, addr) \
    asm volatile("ldmatrix.sync.aligned.m8n8.x4.shared.b16 {%0,%1,%2,%3}, [%4];" \
        : "=r"((r)[0]), "=r"((r)[1]), "=r"((r)[2]), "=r"((r)[3]) : "r"(addr))
#define LDSM_X4T(r, addr) \
    asm volatile("ldmatrix.sync.aligned.m8n8.x4.trans.shared.b16 {%0,%1,%2,%3}, [%4];" \
        : "=r"((r)[0]), "=r"((r)[1]), "=r"((r)[2]), "=r"((r)[3]) : "r"(addr))

#define MMA16816(d, a, b0, b1) \
    asm volatile("mma.sync.aligned.m16n8k16.row.col.f32.f16.f16.f32 " \
        "{%0,%1,%2,%3}, {%4,%5,%6,%7}, {%8,%9}, {%0,%1,%2,%3};" \
        : "+f"((d)[0]), "+f"((d)[1]), "+f"((d)[2]), "+f"((d)[3]) \
        : "r"((a)[0]), "r"((a)[1]), "r"((a)[2]), "r"((a)[3]), "r"(b0), "r"(b1))

#define SWZA(off) ((off) ^ (((off) >> 3) & 0x70))   // 128B rows
#define SWZB(off) ((off) ^ (((off) >> 4) & 0x70))   // 256B rows

// ---------------- scratch ----------------
__device__ __align__(256) float g_x   [NROWS*WDIM];
__device__ __align__(256) float g_y   [NROWS*WDIM];
__device__ __align__(256) float g_rope[4*LTOK*16];
__device__ __align__(256) float g_bqkv[DEPTH*QKVN];

__device__ __align__(256) __half g_yh [NROWS*WDIM];
__device__ __align__(256) __half g_oh [NROWS*WDIM];
__device__ __align__(256) __half g_qh [NROWS*WDIM];
__device__ __align__(256) __half g_kh [NROWS*WDIM];
__device__ __align__(256) __half g_vh [NROWS*WDIM];
__device__ __align__(256) __half g_h1h[NROWS*MLPDIM];

#define C0 589824
__device__ __align__(256) __half g_wh  [37*C0];      // [conv][wo x4][w1 x4][w2 x4]
__device__ __align__(256) __half g_wqkv[12*C0];      // [l][768][2304]

// ---------------- small helpers ----------------
__device__ __forceinline__ float gelu_f(float x) {
    float u = 0.7978845608028654f*(x + 0.044715f*x*x*x);
    float t = __expf(2.f*u);
    float th = 1.f - __fdividef(2.f, t + 1.f);
    return 0.5f*x*(1.f + th);
}

// ---------------- weight convert (conv, wo, w1, w2) ----------------
__global__ void wcvt_k(const float* __restrict__ conv, const float* __restrict__ wo,
                       const float* __restrict__ w1, const float* __restrict__ w2,
                       __half* __restrict__ dst) {
    size_t i4 = ((size_t)blockIdx.x*256 + threadIdx.x) * 4;
    if (i4 >= (size_t)37*C0) return;
    const float* src; size_t off;
    if      (i4 < (size_t)C0)    { src = conv; off = i4; }
    else if (i4 < (size_t)5*C0)  { src = wo;   off = i4 - (size_t)C0; }
    else if (i4 < (size_t)21*C0) { src = w1;   off = i4 - (size_t)5*C0; }
    else                         { src = w2;   off = i4 - (size_t)21*C0; }
    float4 v = *(const float4*)(src + off);
    __half2* d = (__half2*)(dst + i4);
    d[0] = __floats2half2_rn(v.x, v.y);
    d[1] = __floats2half2_rn(v.z, v.w);
}

// ---------------- qkv weight interleave: [l][k][2304] ----------------
__global__ void wqkvcvt_k(const float* __restrict__ wq, const float* __restrict__ wk,
                          const float* __restrict__ wv, __half* __restrict__ dst) {
    size_t i4 = ((size_t)blockIdx.x*256 + threadIdx.x) * 4;
    if (i4 >= (size_t)12*C0) return;
    size_t l  = i4 / ((size_t)WDIM*QKVN);
    size_t r  = i4 % ((size_t)WDIM*QKVN);
    size_t k  = r / QKVN;
    size_t j  = r % QKVN;
    size_t blk = j / WDIM;
    const float* src = (blk == 0) ? wq : (blk == 1) ? wk : wv;
    float4 v = *(const float4*)(src + l*(size_t)C0 + k*WDIM + (j - blk*WDIM));
    __half2* d = (__half2*)(dst + i4);
    d[0] = __floats2half2_rn(v.x, v.y);
    d[1] = __floats2half2_rn(v.z, v.w);
}

__global__ void bcat_k(const float* __restrict__ bq, const float* __restrict__ bk,
                       const float* __restrict__ bv, float* __restrict__ dst) {
    int idx = blockIdx.x*256 + threadIdx.x;
    if (idx >= DEPTH*QKVN) return;
    int l = idx / QKVN, j = idx % QKVN;
    int blk = j / WDIM;
    const float* src = (blk == 0) ? bq : (blk == 1) ? bk : bv;
    dst[idx] = src[l*WDIM + (j - blk*WDIM)];
}

// ---------------- im2col (fp16) ----------------
__global__ void im2col_k(const float* __restrict__ img, __half* __restrict__ oh) {
    int idx = blockIdx.x*256 + threadIdx.x;
    if (idx >= NROWS*WDIM) return;
    int t  = idx % WDIM;
    int nl = idx / WDIM;
    int l  = nl % LTOK;
    int n  = nl / LTOK;
    int ci = t % 3;
    int ij = t / 3;
    int j  = ij % PATCH;
    int i  = ij / PATCH;
    int px = l % GRIDP, py = l / GRIDP;
    float v = img[ (((size_t)n*IMG + (py*PATCH+i))*IMG + (px*PATCH+j))*CIN + ci ];
    oh[idx] = __float2half_rn(v);
}

// ---------------- rope cache ----------------
__global__ void rope_cache_k(float* __restrict__ cache) {
    int idx = blockIdx.x*256 + threadIdx.x;
    if (idx >= LTOK*16) return;
    int f = idx % 16, l = idx / 16;
    float freq = (float)f / (15.f + 1e-9f);
    float inv  = powf(10000.f, -freq);
    float u = ((float)(l % GRIDP) + 0.5f) / (float)GRIDP;
    float v = ((float)(l / GRIDP) + 0.5f) / (float)GRIDP;
    float ax = u*inv, ay = v*inv;
    cache[0*LTOK*16 + idx] = cosf(ax);
    cache[1*LTOK*16 + idx] = sinf(ax);
    cache[2*LTOK*16 + idx] = cosf(ay);
    cache[3*LTOK*16 + idx] = sinf(ay);
}

// ---------------- layernorm: warp per row ----------------
__global__ void ln_k(const float* __restrict__ x, float* __restrict__ y,
                     __half* __restrict__ yh,
                     const float* __restrict__ sc, const float* __restrict__ bi) {
    int wid = threadIdx.x >> 5, lane = threadIdx.x & 31;
    int row = blockIdx.x*8 + wid;
    const float4* xr = (const float4*)(x + (size_t)row*WDIM);
    float4 v[6];
    float s = 0.f, sq = 0.f;
    #pragma unroll
    for (int j = 0; j < 6; j++) {
        v[j] = xr[lane + j*32];
        s  += v[j].x + v[j].y + v[j].z + v[j].w;
        sq += v[j].x*v[j].x + v[j].y*v[j].y + v[j].z*v[j].z + v[j].w*v[j].w;
    }
    #pragma unroll
    for (int o = 16; o; o >>= 1) {
        s  += __shfl_xor_sync(0xffffffffu, s,  o);
        sq += __shfl_xor_sync(0xffffffffu, sq, o);
    }
    float m   = s * (1.f/(float)WDIM);
    float var = sq * (1.f/(float)WDIM) - m*m;
    float inv = rsqrtf(var + EPS);
    size_t base = (size_t)row*WDIM;
    #pragma unroll
    for (int j = 0; j < 6; j++) {
        int c = (lane + j*32)*4;
        float4 scv = *(const float4*)(sc + c);
        float4 biv = *(const float4*)(bi + c);
        float o0 = (v[j].x - m)*inv*scv.x + biv.x;
        float o1 = (v[j].y - m)*inv*scv.y + biv.y;
        float o2 = (v[j].z - m)*inv*scv.z + biv.z;
        float o3 = (v[j].w - m)*inv*scv.w + biv.w;
        if (y) *(float4*)(y + base + c) = make_float4(o0, o1, o2, o3);
        __half2 h0 = __floats2half2_rn(o0, o1);
        __half2 h1 = __floats2half2_rn(o2, o3);
        *(uint2*)(yh + base + c) = make_uint2(*(uint32_t*)&h0, *(uint32_t*)&h1);
    }
}

// ---------------- GEMM core macros (tile 64x128, 128 thr, 3 stages) ----------------
#define GSTAGES 3
#define STAGE_BYTES 24576
#define GEMM_SMEM (GSTAGES*STAGE_BYTES)

#define GEMM_PREAMBLE \
    extern __shared__ __align__(1024) char smem[]; \
    const uint32_t sbase = smem_to_u32(smem); \
    int tid = threadIdx.x; \
    int wid = tid >> 5, lane = tid & 31; \
    int bn = blockIdx.x * 128, bm = blockIdx.y * 64; \
    const __half* Aptr = A + (size_t)bm*K; \
    const int nch = K >> 6; \
    auto issue = [&](int ch, int stg) { \
        uint32_t sA = sbase + stg*STAGE_BYTES; \
        uint32_t sB = sA + 8192; \
        const __half* srcA = Aptr + ch*64; \
        _Pragma("unroll") \
        for (int rr = 0; rr < 4; rr++) { \
            int idx = rr*128 + tid; \
            int row = idx >> 3, u = idx & 7; \
            CP_ASYNC16(sA + SWZA((uint32_t)(row*128 + u*16)), srcA + (size_t)row*K + u*8); \
        } \
        const __half* srcB = B + (size_t)(ch*64)*N + bn; \
        _Pragma("unroll") \
        for (int rr = 0; rr < 8; rr++) { \
            int idx = rr*128 + tid; \
            int row = idx >> 4, u = idx & 15; \
            CP_ASYNC16(sB + SWZB((uint32_t)(row*256 + u*16)), srcB + (size_t)row*N + u*8); \
        } \
    }; \
    int m0w = (wid >> 1) * 32, n0w = (wid & 1) * 64; \
    int jj = lane >> 3, rr8 = lane & 7; \
    int arow = m0w + (jj & 1)*8 + rr8; \
    int acol = (jj >> 1) * 8; \
    int btrow = lane & 15; \
    int btcol = n0w + ((lane >> 4) << 3); \
    float acc[2][8][4]; \
    _Pragma("unroll") \
    for (int mt = 0; mt < 2; mt++) \
        _Pragma("unroll") \
        for (int nt = 0; nt < 8; nt++) \
            _Pragma("unroll") \
            for (int r = 0; r < 4; r++) acc[mt][nt][r] = 0.f; \
    issue(0, 0); CP_COMMIT(); \
    issue(1, 1); CP_COMMIT(); \
    for (int ch = 0; ch < nch; ch++) { \
        if (ch + 2 < nch) issue(ch + 2, (ch + 2) % GSTAGES); \
        CP_COMMIT(); \
        CP_WAIT2(); \
        __syncthreads(); \
        uint32_t sA = sbase + (ch % GSTAGES)*STAGE_BYTES; \
        uint32_t sB = sA + 8192; \
        _Pragma("unroll") \
        for (int kk = 0; kk < 4; kk++) { \
            uint32_t a[2][4]; \
            _Pragma("unroll") \
            for (int mt = 0; mt < 2; mt++) { \
                uint32_t off = (uint32_t)((arow + mt*16)*128 + (kk*16 + acol)*2); \
                LDSM_X4(a[mt], sA + SWZA(off)); \
            } \
            uint32_t bt[4][4]; \
            _Pragma("unroll") \
            for (int np = 0; np < 4; np++) { \
                uint32_t off = (uint32_t)((kk*16 + btrow)*256 + (btcol + np*16)*2); \
                LDSM_X4T(bt[np], sB + SWZB(off)); \
            } \
            _Pragma("unroll") \
            for (int mt = 0; mt < 2; mt++) \
                _Pragma("unroll") \
                for (int nt = 0; nt < 8; nt++) \
                    MMA16816(acc[mt][nt], a[mt], bt[nt>>1][(nt&1)*2], bt[nt>>1][(nt&1)*2+1]); \
        } \
        __syncthreads(); \
    } \
    int lr = lane >> 2, lc = (lane & 3) * 2;

// ---------------- standard GEMM (fp32/fp16 out, residual, gelu) ----------------
template<bool GELU, bool RES, bool HOUT>
__global__ void __launch_bounds__(128, 3)
gemm_mma(const __half* __restrict__ A, const __half* __restrict__ B,
         const float* __restrict__ bias, const float* __restrict__ R,
         float* __restrict__ C, __half* __restrict__ Ch,
         int M, int N, int K) {
    GEMM_PREAMBLE
    #pragma unroll
    for (int mt = 0; mt < 2; mt++) {
        #pragma unroll
        for (int nt = 0; nt < 8; nt++) {
            int col = bn + n0w + nt*8 + lc;
            float b0 = bias[col], b1 = bias[col+1];
            int r0 = bm + m0w + mt*16 + lr;
            #pragma unroll
            for (int half = 0; half < 2; half++) {
                int m = r0 + half*8;
                float v0 = acc[mt][nt][half*2]   + b0;
                float v1 = acc[mt][nt][half*2+1] + b1;
                if (GELU) { v0 = gelu_f(v0); v1 = gelu_f(v1); }
                size_t o = (size_t)m*N + col;
                if (HOUT) {
                    *(__half2*)(Ch + o) = __floats2half2_rn(v0, v1);
                } else {
                    if (RES) {
                        float2 rv = *(const float2*)(R + o);
                        v0 += rv.x; v1 += rv.y;
                    }
                    *(float2*)(C + o) = make_float2(v0, v1);
                }
            }
        }
    }
}

// ---------------- QKV GEMM: rope + head-major fp16 epilogue ----------------
__global__ void __launch_bounds__(128, 3)
gemm_qkv(const __half* __restrict__ A, const __half* __restrict__ B,
         const float* __restrict__ bias, const float* __restrict__ cache,
         __half* __restrict__ Qh, __half* __restrict__ Kh, __half* __restrict__ Vh,
         int M, int N, int K) {
    GEMM_PREAMBLE
    #pragma unroll
    for (int mt = 0; mt < 2; mt++) {
        #pragma unroll
        for (int nt = 0; nt < 8; nt++) {
            int colg = bn + n0w + nt*8 + lc;
            float b0 = bias[colg], b1 = bias[colg+1];
            int plane = colg / WDIM;
            int rem   = colg - plane*WDIM;
            int hh = rem >> 6;
            int d  = rem & 63;          // even
            int p  = d >> 1;
            int r0 = bm + m0w + mt*16 + lr;
            #pragma unroll
            for (int half = 0; half < 2; half++) {
                int m = r0 + half*8;
                int n = m / LTOK, l = m - n*LTOK;
                float v0 = acc[mt][nt][half*2]   + b0;
                float v1 = acc[mt][nt][half*2+1] + b1;
                size_t dsto = ((size_t)(n*NHEAD + hh)*LTOK + l)*HDIM + d;
                if (plane == 2) {
                    *(__half2*)(Vh + dsto) = __floats2half2_rn(v0, v1);
                } else {
                    float c, s;
                    if (p < 16) { c = cache[l*16 + p];             s = cache[LTOK*16 + l*16 + p]; }
                    else        { c = cache[2*LTOK*16 + l*16 + p-16]; s = cache[3*LTOK*16 + l*16 + p-16]; }
                    float rx = v0*c - v1*s;
                    float ry = v0*s + v1*c;
                    if (plane == 0) {
                        rx *= 0.125f; ry *= 0.125f;
                        *(__half2*)(Qh + dsto) = __floats2half2_rn(rx, ry);
                    } else {
                        *(__half2*)(Kh + dsto) = __floats2half2_rn(rx, ry);
                    }
                }
            }
        }
    }
}

// ---------------- single-pass flash attention ----------------
// CTA: 64 q-rows, 4 warps (16 rows each), 128 threads. K/V streamed in 64-key
// chunks, double-buffered. Online softmax; P stays in registers (S-frag -> A-frag).
#define FA_SQ   0
#define FA_K0   8192
#define FA_V0   16384
#define FA_K1   24576
#define FA_V1   32768
#define FA_SMEM 40960

__global__ void __launch_bounds__(128, 3)
fattn_k(const __half* __restrict__ Qh, const __half* __restrict__ Kh,
        const __half* __restrict__ Vh, __half* __restrict__ Oh) {
    extern __shared__ __align__(1024) char smem[];
    const uint32_t sb = smem_to_u32(smem);
    int tid = threadIdx.x;
    int w = tid >> 5, lane = tid & 31;
    int q0 = blockIdx.x * 64;
    int nh = blockIdx.y;
    int h  = nh % NHEAD, n = nh / NHEAD;

    const __half* qbase = Qh + ((size_t)nh*LTOK + q0)*HDIM;
    const __half* kbase = Kh + (size_t)nh*LTOK*HDIM;
    const __half* vbase = Vh + (size_t)nh*LTOK*HDIM;

    auto issue64 = [&](const __half* src, uint32_t dstoff) {
        #pragma unroll
        for (int it = 0; it < 4; it++) {
            int idx = it*128 + tid;
            int row = idx >> 3, u = idx & 7;
            CP_ASYNC16(sb + dstoff + SWZA((uint32_t)(row*128 + u*16)), src + row*HDIM + u*8);
        }
    };

    // prologue: group A = Q + K0 + V0; group B = K1 + V1
    issue64(qbase, FA_SQ);
    issue64(kbase, FA_K0);
    issue64(vbase, FA_V0);
    CP_COMMIT();
    issue64(kbase + 64*HDIM, FA_K1);
    issue64(vbase + 64*HDIM, FA_V1);
    CP_COMMIT();

    float m0 = -1e30f, m1 = -1e30f, l0 = 0.f, l1 = 0.f;
    float od[8][4];
    #pragma unroll
    for (int j = 0; j < 8; j++)
        #pragma unroll
        for (int r = 0; r < 4; r++) od[j][r] = 0.f;
    uint32_t qf[4][4];

    const int NCH = LTOK / 64;   // 9
    for (int c = 0; c < NCH; c++) {
        CP_WAIT1();
        __syncthreads();
        uint32_t kbuf = (c & 1) ? FA_K1 : FA_K0;
        uint32_t vbuf = (c & 1) ? FA_V1 : FA_V0;
        if (c == 0) {
            #pragma unroll
            for (int kk = 0; kk < 4; kk++) {
                uint32_t off = (uint32_t)((w*16 + (lane & 15))*128 + (kk*16 + ((lane>>4)<<3))*2);
                LDSM_X4(qf[kk], sb + FA_SQ + SWZA(off));
            }
        }
        // S = Q K^T (16 x 64 per warp)
        float sf[8][4];
        #pragma unroll
        for (int j = 0; j < 8; j++)
            #pragma unroll
            for (int r = 0; r < 4; r++) sf[j][r] = 0.f;
        #pragma unroll
        for (int kk = 0; kk < 4; kk++) {
            #pragma unroll
            for (int kt = 0; kt < 4; kt++) {
                uint32_t bf[4];
                uint32_t off = (uint32_t)((kt*16 + (lane & 15))*128 + (kk*16 + ((lane>>4)<<3))*2);
                LDSM_X4(bf, sb + kbuf + SWZA(off));
                MMA16816(sf[2*kt],   qf[kk], bf[0], bf[2]);
                MMA16816(sf[2*kt+1], qf[kk], bf[1], bf[3]);
            }
        }
        // online softmax
        float cm0 = -1e30f, cm1 = -1e30f;
        #pragma unroll
        for (int j = 0; j < 8; j++) {
            cm0 = fmaxf(cm0, fmaxf(sf[j][0], sf[j][1]));
            cm1 = fmaxf(cm1, fmaxf(sf[j][2], sf[j][3]));
        }
        cm0 = fmaxf(cm0, __shfl_xor_sync(0xffffffffu, cm0, 1));
        cm0 = fmaxf(cm0, __shfl_xor_sync(0xffffffffu, cm0, 2));
        cm1 = fmaxf(cm1, __shfl_xor_sync(0xffffffffu, cm1, 1));
        cm1 = fmaxf(cm1, __shfl_xor_sync(0xffffffffu, cm1, 2));
        float nm0 = fmaxf(m0, cm0), nm1 = fmaxf(m1, cm1);
        float sc0 = __expf(m0 - nm0), sc1 = __expf(m1 - nm1);
        m0 = nm0; m1 = nm1;
        float rs0 = 0.f, rs1 = 0.f;
        uint32_t pa[4][4];
        #pragma unroll
        for (int t = 0; t < 4; t++) {
            float e00 = __expf(sf[2*t][0]   - m0), e01 = __expf(sf[2*t][1]   - m0);
            float e10 = __expf(sf[2*t][2]   - m1), e11 = __expf(sf[2*t][3]   - m1);
            float e20 = __expf(sf[2*t+1][0] - m0), e21 = __expf(sf[2*t+1][1] - m0);
            float e30 = __expf(sf[2*t+1][2] - m1), e31 = __expf(sf[2*t+1][3] - m1);
            rs0 += e00 + e01 + e20 + e21;
            rs1 += e10 + e11 + e30 + e31;
            __half2 h;
            h = __floats2half2_rn(e00, e01); pa[t][0] = *(uint32_t*)&h;
            h = __floats2half2_rn(e10, e11); pa[t][1] = *(uint32_t*)&h;
            h = __floats2half2_rn(e20, e21); pa[t][2] = *(uint32_t*)&h;
            h = __floats2half2_rn(e30, e31); pa[t][3] = *(uint32_t*)&h;
        }
        rs0 += __shfl_xor_sync(0xffffffffu, rs0, 1);
        rs0 += __shfl_xor_sync(0xffffffffu, rs0, 2);
        rs1 += __shfl_xor_sync(0xffffffffu, rs1, 1);
        rs1 += __shfl_xor_sync(0xffffffffu, rs1, 2);
        l0 = l0*sc0 + rs0;
        l1 = l1*sc1 + rs1;
        #pragma unroll
        for (int j = 0; j < 8; j++) {
            od[j][0] *= sc0; od[j][1] *= sc0;
            od[j][2] *= sc1; od[j][3] *= sc1;
        }
        // O += P V
        #pragma unroll
        for (int t = 0; t < 4; t++) {
            #pragma unroll
            for (int dt = 0; dt < 4; dt++) {
                uint32_t vb[4];
                uint32_t off = (uint32_t)((t*16 + (lane & 15))*128 + (dt*16 + ((lane>>4)<<3))*2);
                LDSM_X4T(vb, sb + vbuf + SWZA(off));
                MMA16816(od[2*dt],   pa[t], vb[0], vb[1]);
                MMA16816(od[2*dt+1], pa[t], vb[2], vb[3]);
            }
        }
        __syncthreads();
        if (c + 2 < NCH) {
            issue64(kbase + (c+2)*64*HDIM, (c & 1) ? FA_K1 : FA_K0);
            issue64(vbase + (c+2)*64*HDIM, (c & 1) ? FA_V1 : FA_V0);
        }
        CP_COMMIT();
    }

    // epilogue
    float inv0 = 1.f / l0, inv1 = 1.f / l1;
    int row = lane >> 2;
    int gq0 = q0 + w*16 + row;
    #pragma unroll
    for (int j = 0; j < 8; j++) {
        int col = j*8 + (lane & 3)*2;
        *(__half2*)(Oh + ((size_t)(n*LTOK + gq0))*WDIM + h*HDIM + col) =
            __floats2half2_rn(od[j][0]*inv0, od[j][1]*inv0);
        *(__half2*)(Oh + ((size_t)(n*LTOK + gq0 + 8))*WDIM + h*HDIM + col) =
            __floats2half2_rn(od[j][2]*inv1, od[j][3]*inv1);
    }
}

// ---------------- final mean ----------------
__global__ void mean_k(const float* __restrict__ y, float* __restrict__ out) {
    int c = blockIdx.x*256 + threadIdx.x;
    int n = blockIdx.y;
    if (c >= WDIM) return;
    float acc = 0.f;
    for (int l = 0; l < LTOK; l++)
        acc += y[(size_t)(n*LTOK + l)*WDIM + c];
    out[(size_t)n*WDIM + c] = acc * (1.f/(float)LTOK);
}

// ---------------- host orchestration ----------------
extern "C" void kernel_launch(void* const* d_in, const int* in_sizes, int n_in,
                              void* d_out, int out_size) {
    const float* image     = (const float*)d_in[0];
    const float* conv_ker  = (const float*)d_in[1];
    const float* conv_bias = (const float*)d_in[2];
    const float* ln1_scale = (const float*)d_in[3];
    const float* ln1_bias  = (const float*)d_in[4];
    const float* wq        = (const float*)d_in[5];
    const float* bq        = (const float*)d_in[6];
    const float* wk        = (const float*)d_in[7];
    const float* bk        = (const float*)d_in[8];
    const float* wv        = (const float*)d_in[9];
    const float* bv        = (const float*)d_in[10];
    const float* wo        = (const float*)d_in[11];
    const float* bo        = (const float*)d_in[12];
    const float* ln2_scale = (const float*)d_in[13];
    const float* ln2_bias  = (const float*)d_in[14];
    const float* w1        = (const float*)d_in[15];
    const float* b1        = (const float*)d_in[16];
    const float* w2        = (const float*)d_in[17];
    const float* b2        = (const float*)d_in[18];
    const float* lnf_scale = (const float*)d_in[19];
    const float* lnf_bias  = (const float*)d_in[20];
    float* out = (float*)d_out;

    float *x, *y, *rope, *bqkv;
    __half *yh, *oh, *qh, *kh, *vh, *h1h, *wh, *wqkvh;
    cudaGetSymbolAddress((void**)&x,    g_x);
    cudaGetSymbolAddress((void**)&y,    g_y);
    cudaGetSymbolAddress((void**)&rope, g_rope);
    cudaGetSymbolAddress((void**)&bqkv, g_bqkv);
    cudaGetSymbolAddress((void**)&yh,   g_yh);
    cudaGetSymbolAddress((void**)&oh,   g_oh);
    cudaGetSymbolAddress((void**)&qh,   g_qh);
    cudaGetSymbolAddress((void**)&kh,   g_kh);
    cudaGetSymbolAddress((void**)&vh,   g_vh);
    cudaGetSymbolAddress((void**)&h1h,  g_h1h);
    cudaGetSymbolAddress((void**)&wh,   g_wh);
    cudaGetSymbolAddress((void**)&wqkvh,g_wqkv);

    cudaFuncSetAttribute(gemm_mma<false,false,false>, cudaFuncAttributeMaxDynamicSharedMemorySize, GEMM_SMEM);
    cudaFuncSetAttribute(gemm_mma<false,true, false>, cudaFuncAttributeMaxDynamicSharedMemorySize, GEMM_SMEM);
    cudaFuncSetAttribute(gemm_mma<true, false,true >, cudaFuncAttributeMaxDynamicSharedMemorySize, GEMM_SMEM);
    cudaFuncSetAttribute(gemm_qkv, cudaFuncAttributeMaxDynamicSharedMemorySize, GEMM_SMEM);
    cudaFuncSetAttribute(fattn_k,  cudaFuncAttributeMaxDynamicSharedMemorySize, FA_SMEM);

    __half* w_conv = wh;
    __half* w_o    = wh + (size_t)1*C0;
    __half* w_1    = wh + (size_t)5*C0;
    __half* w_2    = wh + (size_t)21*C0;

    wcvt_k<<<(unsigned)(((size_t)37*C0/4 + 255)/256), 256>>>(conv_ker, wo, w1, w2, wh);
    wqkvcvt_k<<<(unsigned)(((size_t)12*C0/4 + 255)/256), 256>>>(wq, wk, wv, wqkvh);
    bcat_k<<<(DEPTH*QKVN + 255)/256, 256>>>(bq, bk, bv, bqkv);
    rope_cache_k<<<(LTOK*16 + 255)/256, 256>>>(rope);

    im2col_k<<<(NROWS*WDIM + 255)/256, 256>>>(image, h1h);
    {
        dim3 g(WDIM/128, NROWS/64);
        gemm_mma<false,false,false><<<g, 128, GEMM_SMEM>>>(h1h, w_conv, conv_bias,
                                                           nullptr, x, nullptr,
                                                           NROWS, WDIM, WDIM);
    }

    dim3 gProj(WDIM/128,  NROWS/64);   // 6 x 72
    dim3 gQkv (QKVN/128,  NROWS/64);   // 18 x 72
    dim3 gMlp1(MLPDIM/128,NROWS/64);   // 24 x 72
    dim3 gAttn(LTOK/64, BATCH*NHEAD);  // 9 x 96

    for (int l = 0; l < DEPTH; l++) {
        const __half* wqkv_l = wqkvh + (size_t)l*3*C0;
        const __half* wo_l   = w_o + (size_t)l*C0;
        const __half* w1_l   = w_1 + (size_t)l*4*C0;
        const __half* w2_l   = w_2 + (size_t)l*4*C0;
        const float* bqkv_l = bqkv + (size_t)l*QKVN;
        const float* bo_l = bo + (size_t)l*WDIM;
        const float* b1_l = b1 + (size_t)l*MLPDIM;
        const float* b2_l = b2 + (size_t)l*WDIM;

        ln_k<<<NROWS/8, 256>>>(x, nullptr, yh, ln1_scale + (size_t)l*WDIM, ln1_bias + (size_t)l*WDIM);

        gemm_qkv<<<gQkv, 128, GEMM_SMEM>>>(yh, wqkv_l, bqkv_l, rope, qh, kh, vh, NROWS, QKVN, WDIM);

        fattn_k<<<gAttn, 128, FA_SMEM>>>(qh, kh, vh, oh);

        gemm_mma<false,true,false><<<gProj, 128, GEMM_SMEM>>>(oh, wo_l, bo_l, x, x, nullptr, NROWS, WDIM, WDIM);

        ln_k<<<NROWS/8, 256>>>(x, nullptr, yh, ln2_scale + (size_t)l*WDIM, ln2_bias + (size_t)l*WDIM);

        gemm_mma<true,false,true><<<gMlp1, 128, GEMM_SMEM>>>(yh, w1_l, b1_l, nullptr, nullptr, h1h, NROWS, MLPDIM, WDIM);
        gemm_mma<false,true,false><<<gProj, 128, GEMM_SMEM>>>(h1h, w2_l, b2_l, x, x, nullptr, NROWS, WDIM, MLPDIM);
    }

    ln_k<<<NROWS/8, 256>>>(x, y, yh, lnf_scale, lnf_bias);
    {
        dim3 g((WDIM + 255)/256, BATCH);
        mean_k<<<g, 256>>>(y, out);
    }
}